// round 1
// baseline (speedup 1.0000x reference)
#include <cuda_runtime.h>
#include <math.h>

#define NN 100000
#define EE 1600000
#define HH 128
#define CC 40

// ---------------- scratch (no allocations allowed) ----------------
__device__ float g_hpre[NN * HH];
__device__ float g_h1[NN * HH];
__device__ float g_h2[NN * HH];
__device__ float g_dinv[NN];
__device__ int   g_deg[NN];
__device__ int   g_rowptr[NN + 1];
__device__ int   g_cursor[NN];
__device__ int   g_esrc[EE];

// ---------------- CSR build ----------------
__global__ void zero_deg_kernel() {
    int i = blockIdx.x * blockDim.x + threadIdx.x;
    if (i < NN) g_deg[i] = 0;
}

__global__ void count_kernel(const int* __restrict__ dst) {
    int e = blockIdx.x * blockDim.x + threadIdx.x;
    if (e < EE) atomicAdd(&g_deg[dst[e]], 1);
}

__global__ void dinv_kernel() {
    int i = blockIdx.x * blockDim.x + threadIdx.x;
    if (i < NN) g_dinv[i] = rsqrtf((float)g_deg[i] + 1.0f);
}

// single-block exclusive scan of g_deg -> g_rowptr (100k elems, ~10us)
__global__ void scan_kernel() {
    __shared__ int warp_off[32];
    __shared__ int s_carry;
    const int tid = threadIdx.x;
    const int lane = tid & 31, wid = tid >> 5;
    if (tid == 0) { s_carry = 0; g_rowptr[0] = 0; }
    __syncthreads();
    for (int base = 0; base < NN; base += 1024) {
        int i = base + tid;
        int v = (i < NN) ? g_deg[i] : 0;
        int inc = v;
        #pragma unroll
        for (int d = 1; d < 32; d <<= 1) {
            int t = __shfl_up_sync(0xFFFFFFFFu, inc, d);
            if (lane >= d) inc += t;
        }
        if (lane == 31) warp_off[wid] = inc;
        __syncthreads();
        if (wid == 0) {
            int ws = warp_off[lane];
            int wi = ws;
            #pragma unroll
            for (int d = 1; d < 32; d <<= 1) {
                int t = __shfl_up_sync(0xFFFFFFFFu, wi, d);
                if (lane >= d) wi += t;
            }
            warp_off[lane] = wi - ws;  // exclusive warp offset
        }
        __syncthreads();
        int val = s_carry + warp_off[wid] + inc;  // inclusive scan value
        if (i < NN) g_rowptr[i + 1] = val;
        __syncthreads();
        if (tid == 1023) s_carry = val;
        __syncthreads();
    }
}

__global__ void cursor_kernel() {
    int i = blockIdx.x * blockDim.x + threadIdx.x;
    if (i < NN) g_cursor[i] = g_rowptr[i];
}

__global__ void fill_kernel(const int* __restrict__ src, const int* __restrict__ dst) {
    int e = blockIdx.x * blockDim.x + threadIdx.x;
    if (e < EE) {
        int d = dst[e];
        int pos = atomicAdd(&g_cursor[d], 1);
        g_esrc[pos] = src[e];
    }
}

// ---------------- dense GEMM: C[N,128] = A[N,128] @ W[128,128] ----------------
// block: 256 threads, 64 rows x 128 cols; thread: 4 rows x 8 cols
__global__ void __launch_bounds__(256) gemm128_kernel(const float* __restrict__ A,
                                                      const float* __restrict__ W,
                                                      float* __restrict__ C) {
    __shared__ float ws[32][132];
    __shared__ float xs[64][36];
    const int t = threadIdx.x;
    const int cg = t & 15;        // col group: cols cg*8 .. cg*8+7
    const int rg = t >> 4;        // row group: rows rg*4 .. rg*4+3
    const int row0 = blockIdx.x * 64;

    float acc[4][8];
    #pragma unroll
    for (int r = 0; r < 4; r++)
        #pragma unroll
        for (int c = 0; c < 8; c++) acc[r][c] = 0.0f;

    for (int kc = 0; kc < 128; kc += 32) {
        // stage W chunk [32][128]: 1024 float4, 4 per thread
        #pragma unroll
        for (int i = t; i < 1024; i += 256) {
            int r = i >> 5, c4 = i & 31;
            float4 v = *reinterpret_cast<const float4*>(&W[(kc + r) * 128 + c4 * 4]);
            *reinterpret_cast<float4*>(&ws[r][c4 * 4]) = v;
        }
        // stage A chunk [64][32]: 512 float4, 2 per thread
        #pragma unroll
        for (int i = t; i < 512; i += 256) {
            int r = i >> 3, c4 = i & 7;
            int gr = row0 + r;
            float4 v = make_float4(0.f, 0.f, 0.f, 0.f);
            if (gr < NN) v = *reinterpret_cast<const float4*>(&A[gr * 128 + kc + c4 * 4]);
            *reinterpret_cast<float4*>(&xs[r][c4 * 4]) = v;
        }
        __syncthreads();
        #pragma unroll
        for (int k0 = 0; k0 < 32; k0 += 4) {
            float4 xa[4];
            #pragma unroll
            for (int r = 0; r < 4; r++)
                xa[r] = *reinterpret_cast<float4*>(&xs[rg * 4 + r][k0]);
            #pragma unroll
            for (int kk = 0; kk < 4; kk++) {
                float4 w0 = *reinterpret_cast<float4*>(&ws[k0 + kk][cg * 8]);
                float4 w1 = *reinterpret_cast<float4*>(&ws[k0 + kk][cg * 8 + 4]);
                #pragma unroll
                for (int r = 0; r < 4; r++) {
                    float a = (kk == 0) ? xa[r].x : (kk == 1) ? xa[r].y
                            : (kk == 2) ? xa[r].z : xa[r].w;
                    acc[r][0] += a * w0.x; acc[r][1] += a * w0.y;
                    acc[r][2] += a * w0.z; acc[r][3] += a * w0.w;
                    acc[r][4] += a * w1.x; acc[r][5] += a * w1.y;
                    acc[r][6] += a * w1.z; acc[r][7] += a * w1.w;
                }
            }
        }
        __syncthreads();
    }
    #pragma unroll
    for (int r = 0; r < 4; r++) {
        int gr = row0 + rg * 4 + r;
        if (gr < NN) {
            float4 o0 = make_float4(acc[r][0], acc[r][1], acc[r][2], acc[r][3]);
            float4 o1 = make_float4(acc[r][4], acc[r][5], acc[r][6], acc[r][7]);
            *reinterpret_cast<float4*>(&C[gr * 128 + cg * 8])     = o0;
            *reinterpret_cast<float4*>(&C[gr * 128 + cg * 8 + 4]) = o1;
        }
    }
}

// ---------------- aggregation: one warp per node, register accumulation ----------------
__global__ void __launch_bounds__(256) agg_kernel(const float* __restrict__ hpre,
                                                  const float* __restrict__ bias,
                                                  float* __restrict__ hout) {
    int warp = (blockIdx.x * blockDim.x + threadIdx.x) >> 5;
    int lane = threadIdx.x & 31;
    if (warp >= NN) return;
    const int u = warp;
    const float du = g_dinv[u];

    float4 acc = *reinterpret_cast<const float4*>(&hpre[(size_t)u * 128 + lane * 4]);
    const float selfc = du * du;
    acc.x *= selfc; acc.y *= selfc; acc.z *= selfc; acc.w *= selfc;

    const int beg = g_rowptr[u], end = g_rowptr[u + 1];
    int s = (beg < end) ? g_esrc[beg] : 0;
    for (int j = beg; j < end; j++) {
        int snext = (j + 1 < end) ? g_esrc[j + 1] : 0;
        float c = g_dinv[s] * du;
        float4 hv = *reinterpret_cast<const float4*>(&hpre[(size_t)s * 128 + lane * 4]);
        acc.x += hv.x * c; acc.y += hv.y * c;
        acc.z += hv.z * c; acc.w += hv.w * c;
        s = snext;
    }
    float4 bb = *reinterpret_cast<const float4*>(&bias[lane * 4]);
    acc.x = fmaxf(acc.x + bb.x, 0.f);
    acc.y = fmaxf(acc.y + bb.y, 0.f);
    acc.z = fmaxf(acc.z + bb.z, 0.f);
    acc.w = fmaxf(acc.w + bb.w, 0.f);
    *reinterpret_cast<float4*>(&hout[(size_t)u * 128 + lane * 4]) = acc;
}

// ---------------- final: out[N,40] = [h1|h2] @ Wlin + blin ----------------
// block: 256 threads, 64 rows x 40 cols; thread: 2 rows x 5 cols
__global__ void __launch_bounds__(256) gemmout_kernel(const float* __restrict__ h1,
                                                      const float* __restrict__ h2,
                                                      const float* __restrict__ Wlin,
                                                      const float* __restrict__ blin,
                                                      float* __restrict__ out) {
    __shared__ float hs[64][68];
    __shared__ float wl[64][40];
    const int t = threadIdx.x;
    const int cg = t & 7;    // cols cg*5 .. cg*5+4
    const int rg = t >> 3;   // rows rg*2, rg*2+1
    const int row0 = blockIdx.x * 64;

    float acc[2][5];
    #pragma unroll
    for (int r = 0; r < 2; r++)
        #pragma unroll
        for (int c = 0; c < 5; c++) acc[r][c] = 0.0f;

    for (int kc = 0; kc < 256; kc += 64) {
        const float* hsrc = (kc < 128) ? h1 : h2;
        const int koff = (kc < 128) ? kc : kc - 128;
        #pragma unroll
        for (int i = t; i < 1024; i += 256) {  // 64x64 floats = 1024 float4
            int r = i >> 4, c4 = i & 15;
            int gr = row0 + r;
            float4 v = make_float4(0.f, 0.f, 0.f, 0.f);
            if (gr < NN) v = *reinterpret_cast<const float4*>(&hsrc[(size_t)gr * 128 + koff + c4 * 4]);
            *reinterpret_cast<float4*>(&hs[r][c4 * 4]) = v;
        }
        #pragma unroll
        for (int i = t; i < 2560; i += 256) {  // 64x40 floats
            int r = i / 40, c = i % 40;
            wl[r][c] = Wlin[(kc + r) * 40 + c];
        }
        __syncthreads();
        #pragma unroll 8
        for (int k = 0; k < 64; k++) {
            float x0 = hs[rg * 2][k];
            float x1 = hs[rg * 2 + 1][k];
            #pragma unroll
            for (int c = 0; c < 5; c++) {
                float w = wl[k][cg * 5 + c];
                acc[0][c] += x0 * w;
                acc[1][c] += x1 * w;
            }
        }
        __syncthreads();
    }
    #pragma unroll
    for (int r = 0; r < 2; r++) {
        int gr = row0 + rg * 2 + r;
        if (gr < NN) {
            #pragma unroll
            for (int c = 0; c < 5; c++)
                out[(size_t)gr * 40 + cg * 5 + c] = acc[r][c] + blin[cg * 5 + c];
        }
    }
}

// ---------------- log_softmax over 40 classes, in place ----------------
__global__ void __launch_bounds__(256) lsm_kernel(float* __restrict__ out) {
    int warp = (blockIdx.x * blockDim.x + threadIdx.x) >> 5;
    int lane = threadIdx.x & 31;
    if (warp >= NN) return;
    float* p = out + (size_t)warp * 40;
    float v0 = p[lane];                                  // lanes 0..31 all valid (<40)
    float v1 = (lane < 8) ? p[32 + lane] : -INFINITY;
    float m = fmaxf(v0, v1);
    #pragma unroll
    for (int d = 16; d > 0; d >>= 1)
        m = fmaxf(m, __shfl_xor_sync(0xFFFFFFFFu, m, d));
    float s = expf(v0 - m) + ((lane < 8) ? expf(v1 - m) : 0.f);
    #pragma unroll
    for (int d = 16; d > 0; d >>= 1)
        s += __shfl_xor_sync(0xFFFFFFFFu, s, d);
    float lse = m + logf(s);
    p[lane] = v0 - lse;
    if (lane < 8) p[32 + lane] = v1 - lse;
}

// ---------------- launch ----------------
extern "C" void kernel_launch(void* const* d_in, const int* in_sizes, int n_in,
                              void* d_out, int out_size) {
    const float* x    = (const float*)d_in[0];
    const int*   ei   = (const int*)d_in[1];
    const float* W1   = (const float*)d_in[2];
    const float* b1   = (const float*)d_in[3];
    const float* W2   = (const float*)d_in[4];
    const float* b2   = (const float*)d_in[5];
    const float* Wlin = (const float*)d_in[6];
    const float* blin = (const float*)d_in[7];
    float* out = (float*)d_out;

    const int* src = ei;        // edge_index[0]
    const int* dst = ei + EE;   // edge_index[1]

    float *p_hpre, *p_h1, *p_h2;
    cudaGetSymbolAddress((void**)&p_hpre, g_hpre);
    cudaGetSymbolAddress((void**)&p_h1, g_h1);
    cudaGetSymbolAddress((void**)&p_h2, g_h2);

    const int NB_N = (NN + 255) / 256;     // 391
    const int NB_E = (EE + 255) / 256;     // 6250
    const int NB_W = (NN * 32 + 255) / 256; // warp-per-node grids: 12500
    const int NB_G = (NN + 63) / 64;       // 1563

    zero_deg_kernel<<<NB_N, 256>>>();
    count_kernel<<<NB_E, 256>>>(dst);
    dinv_kernel<<<NB_N, 256>>>();
    scan_kernel<<<1, 1024>>>();
    cursor_kernel<<<NB_N, 256>>>();
    fill_kernel<<<NB_E, 256>>>(src, dst);

    gemm128_kernel<<<NB_G, 256>>>(x, W1, p_hpre);
    agg_kernel<<<NB_W, 256>>>(p_hpre, b1, p_h1);

    gemm128_kernel<<<NB_G, 256>>>(p_h1, W2, p_hpre);
    agg_kernel<<<NB_W, 256>>>(p_hpre, b2, p_h2);

    gemmout_kernel<<<NB_G, 256>>>(p_h1, p_h2, Wlin, blin, out);
    lsm_kernel<<<NB_W, 256>>>(out);
}

// round 3
// speedup vs baseline: 1.4527x; 1.4527x over previous
#include <cuda_runtime.h>
#include <math.h>

#define NN 100000
#define EE 1600000
#define HH 128
#define CC 40
#define NBLK 196   // ceil(100000/512)

// ---------------- scratch (no allocations allowed) ----------------
__device__ float g_hpre[NN * HH];
__device__ float g_h1[NN * HH];
__device__ float g_h2[NN * HH];
__device__ float g_dinv[NN];
__device__ int   g_deg[NN];
__device__ int   g_rowptr[NN + 1];
__device__ int   g_cursor[NN];
__device__ int   g_esrc[EE];
__device__ int   g_bsum[NBLK];
__device__ int   g_boff[NBLK];

// ---------------- f32x2 helpers ----------------
__device__ __forceinline__ unsigned long long fma2(unsigned long long a,
                                                   unsigned long long b,
                                                   unsigned long long c) {
    unsigned long long d;
    asm("fma.rn.f32x2 %0, %1, %2, %3;" : "=l"(d) : "l"(a), "l"(b), "l"(c));
    return d;
}
__device__ __forceinline__ unsigned long long pk2(float lo, float hi) {
    unsigned long long d;
    asm("mov.b64 %0, {%1, %2};" : "=l"(d) : "f"(lo), "f"(hi));
    return d;
}
__device__ __forceinline__ float2 upk(unsigned long long v) {
    float2 r;
    asm("mov.b64 {%0, %1}, %2;" : "=f"(r.x), "=f"(r.y) : "l"(v));
    return r;
}

// ---------------- CSR build ----------------
__global__ void zero_deg_kernel() {
    int i = blockIdx.x * blockDim.x + threadIdx.x;
    if (i < NN) g_deg[i] = 0;
}

__global__ void count_kernel(const int* __restrict__ dst) {
    int e = blockIdx.x * blockDim.x + threadIdx.x;
    if (e < EE) atomicAdd(&g_deg[dst[e]], 1);
}

// block partial sums of deg (512 elems per block)
__global__ void __launch_bounds__(512) blocksum_kernel() {
    __shared__ int wsum[16];
    int t = threadIdx.x, lane = t & 31, wid = t >> 5;
    int i = blockIdx.x * 512 + t;
    int v = (i < NN) ? g_deg[i] : 0;
    #pragma unroll
    for (int d = 16; d > 0; d >>= 1)
        v += __shfl_xor_sync(0xFFFFFFFFu, v, d);
    if (lane == 0) wsum[wid] = v;
    __syncthreads();
    if (wid == 0) {
        int s = (lane < 16) ? wsum[lane] : 0;
        #pragma unroll
        for (int d = 8; d > 0; d >>= 1)
            s += __shfl_xor_sync(0xFFFFFFFFu, s, d);
        if (lane == 0) g_bsum[blockIdx.x] = s;
    }
}

// single block scans NBLK partials -> exclusive offsets
__global__ void __launch_bounds__(256) scanpart_kernel() {
    __shared__ int wsum[8];
    int t = threadIdx.x, lane = t & 31, wid = t >> 5;
    int v = (t < NBLK) ? g_bsum[t] : 0;
    int inc = v;
    #pragma unroll
    for (int d = 1; d < 32; d <<= 1) {
        int u = __shfl_up_sync(0xFFFFFFFFu, inc, d);
        if (lane >= d) inc += u;
    }
    if (lane == 31) wsum[wid] = inc;
    __syncthreads();
    if (wid == 0) {
        int s = (lane < 8) ? wsum[lane] : 0;
        int si = s;
        #pragma unroll
        for (int d = 1; d < 8; d <<= 1) {
            int u = __shfl_up_sync(0xFFFFFFFFu, si, d);
            if (lane >= d) si += u;
        }
        if (lane < 8) wsum[lane] = si - s;  // exclusive
    }
    __syncthreads();
    if (t < NBLK) g_boff[t] = wsum[wid] + inc - v;  // exclusive scan
}

// per-block rescan -> rowptr, cursor, dinv (fused)
__global__ void __launch_bounds__(512) rowptr_kernel() {
    __shared__ int wsum[16];
    int t = threadIdx.x, lane = t & 31, wid = t >> 5;
    int i = blockIdx.x * 512 + t;
    int v = (i < NN) ? g_deg[i] : 0;
    int inc = v;
    #pragma unroll
    for (int d = 1; d < 32; d <<= 1) {
        int u = __shfl_up_sync(0xFFFFFFFFu, inc, d);
        if (lane >= d) inc += u;
    }
    if (lane == 31) wsum[wid] = inc;
    __syncthreads();
    if (wid == 0) {
        int s = (lane < 16) ? wsum[lane] : 0;
        int si = s;
        #pragma unroll
        for (int d = 1; d < 16; d <<= 1) {
            int u = __shfl_up_sync(0xFFFFFFFFu, si, d);
            if (lane >= d) si += u;
        }
        if (lane < 16) wsum[lane] = si - s;  // exclusive
    }
    __syncthreads();
    int incl = g_boff[blockIdx.x] + wsum[wid] + inc;
    if (i < NN) {
        g_rowptr[i + 1] = incl;
        g_cursor[i] = incl - v;
        g_dinv[i] = rsqrtf((float)v + 1.0f);
    }
    if (i == 0) g_rowptr[0] = 0;
}

__global__ void fill_kernel(const int* __restrict__ src, const int* __restrict__ dst) {
    int e = blockIdx.x * blockDim.x + threadIdx.x;
    if (e < EE) {
        int d = dst[e];
        int pos = atomicAdd(&g_cursor[d], 1);
        g_esrc[pos] = src[e];
    }
}

// ---------------- dense GEMM: C[N,128] = A[N,128] @ W[128,128] ----------------
// 128x128 tile, 256 threads (16x16), thread: 8 rows x 8 cols, f32x2 FMA
__global__ void __launch_bounds__(256, 2) gemm128_kernel(const float* __restrict__ A,
                                                         const float* __restrict__ W,
                                                         float* __restrict__ C) {
    __shared__ float ws[32][132];
    __shared__ float xs[128][36];
    const int t = threadIdx.x;
    const int tx = t & 15;         // col group: cols tx*8 .. tx*8+7
    const int ty = t >> 4;         // row group: rows ty*8 .. ty*8+7
    const int row0 = blockIdx.x * 128;

    unsigned long long acc[8][4];
    #pragma unroll
    for (int r = 0; r < 8; r++)
        #pragma unroll
        for (int p = 0; p < 4; p++) acc[r][p] = 0ULL;

    for (int kc = 0; kc < 128; kc += 32) {
        // stage W chunk [32][128]: 1024 float4
        #pragma unroll
        for (int i = t; i < 1024; i += 256) {
            int r = i >> 5, c4 = i & 31;
            float4 v = *reinterpret_cast<const float4*>(&W[(kc + r) * 128 + c4 * 4]);
            *reinterpret_cast<float4*>(&ws[r][c4 * 4]) = v;
        }
        // stage A chunk [128][32]: 1024 float4
        #pragma unroll
        for (int i = t; i < 1024; i += 256) {
            int r = i >> 3, c4 = i & 7;
            int gr = row0 + r;
            float4 v = make_float4(0.f, 0.f, 0.f, 0.f);
            if (gr < NN) v = *reinterpret_cast<const float4*>(&A[(size_t)gr * 128 + kc + c4 * 4]);
            *reinterpret_cast<float4*>(&xs[r][c4 * 4]) = v;
        }
        __syncthreads();
        #pragma unroll
        for (int k0 = 0; k0 < 32; k0 += 4) {
            float4 xa[8];
            #pragma unroll
            for (int r = 0; r < 8; r++)
                xa[r] = *reinterpret_cast<float4*>(&xs[ty * 8 + r][k0]);
            #pragma unroll
            for (int kk = 0; kk < 4; kk++) {
                const ulonglong2* wp = reinterpret_cast<const ulonglong2*>(&ws[k0 + kk][tx * 8]);
                ulonglong2 wA = wp[0];
                ulonglong2 wB = wp[1];
                #pragma unroll
                for (int r = 0; r < 8; r++) {
                    float a = (kk == 0) ? xa[r].x : (kk == 1) ? xa[r].y
                            : (kk == 2) ? xa[r].z : xa[r].w;
                    unsigned long long aa = pk2(a, a);
                    acc[r][0] = fma2(aa, wA.x, acc[r][0]);
                    acc[r][1] = fma2(aa, wA.y, acc[r][1]);
                    acc[r][2] = fma2(aa, wB.x, acc[r][2]);
                    acc[r][3] = fma2(aa, wB.y, acc[r][3]);
                }
            }
        }
        __syncthreads();
    }
    #pragma unroll
    for (int r = 0; r < 8; r++) {
        int gr = row0 + ty * 8 + r;
        if (gr < NN) {
            float2 p0 = upk(acc[r][0]), p1 = upk(acc[r][1]);
            float2 p2 = upk(acc[r][2]), p3 = upk(acc[r][3]);
            float4 o0 = make_float4(p0.x, p0.y, p1.x, p1.y);
            float4 o1 = make_float4(p2.x, p2.y, p3.x, p3.y);
            *reinterpret_cast<float4*>(&C[(size_t)gr * 128 + tx * 8])     = o0;
            *reinterpret_cast<float4*>(&C[(size_t)gr * 128 + tx * 8 + 4]) = o1;
        }
    }
}

// ---------------- aggregation: one warp per node, shfl-broadcast edge chunks ----------------
__global__ void __launch_bounds__(256) agg_kernel(const float* __restrict__ hpre,
                                                  const float* __restrict__ bias,
                                                  float* __restrict__ hout) {
    int warp = (blockIdx.x * blockDim.x + threadIdx.x) >> 5;
    int lane = threadIdx.x & 31;
    if (warp >= NN) return;
    const int u = warp;
    const float du = g_dinv[u];

    float4 acc = *reinterpret_cast<const float4*>(&hpre[(size_t)u * 128 + lane * 4]);
    const float selfc = du * du;
    acc.x *= selfc; acc.y *= selfc; acc.z *= selfc; acc.w *= selfc;

    const int beg = g_rowptr[u], end = g_rowptr[u + 1];
    for (int base = beg; base < end; base += 32) {
        int rem = end - base;
        int n = rem < 32 ? rem : 32;
        int s = 0; float c = 0.f;
        if (lane < n) {
            s = g_esrc[base + lane];
            c = g_dinv[s] * du;
        }
        #pragma unroll 4
        for (int k = 0; k < n; k++) {
            int   sk = __shfl_sync(0xFFFFFFFFu, s, k);
            float ck = __shfl_sync(0xFFFFFFFFu, c, k);
            float4 hv = __ldg(reinterpret_cast<const float4*>(&hpre[(size_t)sk * 128]) + lane);
            acc.x += hv.x * ck; acc.y += hv.y * ck;
            acc.z += hv.z * ck; acc.w += hv.w * ck;
        }
    }
    float4 bb = *reinterpret_cast<const float4*>(&bias[lane * 4]);
    acc.x = fmaxf(acc.x + bb.x, 0.f);
    acc.y = fmaxf(acc.y + bb.y, 0.f);
    acc.z = fmaxf(acc.z + bb.z, 0.f);
    acc.w = fmaxf(acc.w + bb.w, 0.f);
    *reinterpret_cast<float4*>(&hout[(size_t)u * 128 + lane * 4]) = acc;
}

// ---------------- final: out[N,40] = [h1|h2] @ Wlin + blin ----------------
// 256 rows x 40 cols per block; 256 threads (8 cg x 32 rg); thread: 8 rows x 5 cols
// h staged k-major (transposed) so row pairs load as packed 8-byte units.
__global__ void __launch_bounds__(256, 2) gemmout_kernel(const float* __restrict__ h1,
                                                         const float* __restrict__ h2,
                                                         const float* __restrict__ Wlin,
                                                         const float* __restrict__ blin,
                                                         float* __restrict__ out) {
    __shared__ float hs[32][260];   // [k][row], pad 260
    __shared__ float wl[32][40];
    const int t = threadIdx.x;
    const int cg = t & 7;     // cols cg*5 .. cg*5+4
    const int rg = t >> 3;    // rows rg*8 .. rg*8+7
    const int row0 = blockIdx.x * 256;

    unsigned long long acc[4][5];   // 4 row-pairs x 5 cols
    #pragma unroll
    for (int j = 0; j < 4; j++)
        #pragma unroll
        for (int c = 0; c < 5; c++) acc[j][c] = 0ULL;

    for (int kc = 0; kc < 256; kc += 32) {
        const float* hsrc = (kc < 128) ? h1 : h2;
        const int koff = kc & 127;
        // stage h chunk transposed: 256 rows x 32 k
        #pragma unroll
        for (int i = t; i < 2048; i += 256) {
            int r = i >> 3, k4 = i & 7;
            int gr = row0 + r;
            float4 v = make_float4(0.f, 0.f, 0.f, 0.f);
            if (gr < NN) v = *reinterpret_cast<const float4*>(&hsrc[(size_t)gr * 128 + koff + k4 * 4]);
            hs[k4 * 4 + 0][r] = v.x;
            hs[k4 * 4 + 1][r] = v.y;
            hs[k4 * 4 + 2][r] = v.z;
            hs[k4 * 4 + 3][r] = v.w;
        }
        // stage Wlin chunk 32x40
        #pragma unroll
        for (int i = t; i < 1280; i += 256) {
            int r = i / 40, c = i % 40;
            wl[r][c] = Wlin[(kc + r) * 40 + c];
        }
        __syncthreads();
        #pragma unroll
        for (int k = 0; k < 32; k++) {
            const ulonglong2* xp = reinterpret_cast<const ulonglong2*>(&hs[k][rg * 8]);
            ulonglong2 xA = xp[0];
            ulonglong2 xB = xp[1];
            #pragma unroll
            for (int c = 0; c < 5; c++) {
                float w = wl[k][cg * 5 + c];
                unsigned long long ww = pk2(w, w);
                acc[0][c] = fma2(xA.x, ww, acc[0][c]);
                acc[1][c] = fma2(xA.y, ww, acc[1][c]);
                acc[2][c] = fma2(xB.x, ww, acc[2][c]);
                acc[3][c] = fma2(xB.y, ww, acc[3][c]);
            }
        }
        __syncthreads();
    }
    #pragma unroll
    for (int j = 0; j < 4; j++) {
        int gr0 = row0 + rg * 8 + 2 * j;
        #pragma unroll
        for (int c = 0; c < 5; c++) {
            float2 p = upk(acc[j][c]);
            float b = blin[cg * 5 + c];
            if (gr0 < NN)     out[(size_t)gr0 * 40 + cg * 5 + c]       = p.x + b;
            if (gr0 + 1 < NN) out[(size_t)(gr0 + 1) * 40 + cg * 5 + c] = p.y + b;
        }
    }
}

// ---------------- log_softmax over 40 classes, in place ----------------
__global__ void __launch_bounds__(256) lsm_kernel(float* __restrict__ out) {
    int warp = (blockIdx.x * blockDim.x + threadIdx.x) >> 5;
    int lane = threadIdx.x & 31;
    if (warp >= NN) return;
    float* p = out + (size_t)warp * 40;
    float v0 = p[lane];
    float v1 = (lane < 8) ? p[32 + lane] : -INFINITY;
    float m = fmaxf(v0, v1);
    #pragma unroll
    for (int d = 16; d > 0; d >>= 1)
        m = fmaxf(m, __shfl_xor_sync(0xFFFFFFFFu, m, d));
    float s = expf(v0 - m) + ((lane < 8) ? expf(v1 - m) : 0.f);
    #pragma unroll
    for (int d = 16; d > 0; d >>= 1)
        s += __shfl_xor_sync(0xFFFFFFFFu, s, d);
    float lse = m + logf(s);
    p[lane] = v0 - lse;
    if (lane < 8) p[32 + lane] = v1 - lse;
}

// ---------------- launch ----------------
extern "C" void kernel_launch(void* const* d_in, const int* in_sizes, int n_in,
                              void* d_out, int out_size) {
    const float* x    = (const float*)d_in[0];
    const int*   ei   = (const int*)d_in[1];
    const float* W1   = (const float*)d_in[2];
    const float* b1   = (const float*)d_in[3];
    const float* W2   = (const float*)d_in[4];
    const float* b2   = (const float*)d_in[5];
    const float* Wlin = (const float*)d_in[6];
    const float* blin = (const float*)d_in[7];
    float* out = (float*)d_out;

    const int* src = ei;        // edge_index[0]
    const int* dst = ei + EE;   // edge_index[1]

    float *p_hpre, *p_h1, *p_h2;
    cudaGetSymbolAddress((void**)&p_hpre, g_hpre);
    cudaGetSymbolAddress((void**)&p_h1, g_h1);
    cudaGetSymbolAddress((void**)&p_h2, g_h2);

    const int NB_N = (NN + 255) / 256;
    const int NB_E = (EE + 255) / 256;
    const int NB_W = (NN * 32 + 255) / 256;   // warp-per-node grids
    const int NB_G128 = (NN + 127) / 128;
    const int NB_G256 = (NN + 255) / 256;

    zero_deg_kernel<<<NB_N, 256>>>();
    count_kernel<<<NB_E, 256>>>(dst);
    blocksum_kernel<<<NBLK, 512>>>();
    scanpart_kernel<<<1, 256>>>();
    rowptr_kernel<<<NBLK, 512>>>();
    fill_kernel<<<NB_E, 256>>>(src, dst);

    gemm128_kernel<<<NB_G128, 256>>>(x, W1, p_hpre);
    agg_kernel<<<NB_W, 256>>>(p_hpre, b1, p_h1);

    gemm128_kernel<<<NB_G128, 256>>>(p_h1, W2, p_hpre);
    agg_kernel<<<NB_W, 256>>>(p_hpre, b2, p_h2);

    gemmout_kernel<<<NB_G256, 256>>>(p_h1, p_h2, Wlin, blin, out);
    lsm_kernel<<<NB_W, 256>>>(out);
}

// round 5
// speedup vs baseline: 1.4874x; 1.0239x over previous
#include <cuda_runtime.h>
#include <math.h>

#define NN 100000
#define EE 1600000
#define HH 128
#define CC 40
#define NBLK 196        // ceil(100000/512)
#define NB_E 6250       // ceil(EE/256)
#define GHALF 391       // gemm blocks per half (391*128 = 50048 rows)

// ---------------- scratch (no allocations allowed) ----------------
__device__ float g_hpre[NN * HH];
__device__ float g_h1[NN * HH];
__device__ float g_h2[NN * HH];
__device__ float g_dinv[NN];
__device__ int   g_deg[NN];
__device__ int   g_rowptr[NN + 1];
__device__ int   g_cursor[NN];
__device__ int   g_esrc[EE];
__device__ int   g_bsum[NBLK];
__device__ int   g_boff[NBLK];

// ---------------- f32x2 helpers ----------------
__device__ __forceinline__ unsigned long long fma2(unsigned long long a,
                                                   unsigned long long b,
                                                   unsigned long long c) {
    unsigned long long d;
    asm("fma.rn.f32x2 %0, %1, %2, %3;" : "=l"(d) : "l"(a), "l"(b), "l"(c));
    return d;
}
__device__ __forceinline__ unsigned long long pk2(float lo, float hi) {
    unsigned long long d;
    asm("mov.b64 %0, {%1, %2};" : "=l"(d) : "f"(lo), "f"(hi));
    return d;
}
__device__ __forceinline__ float2 upk(unsigned long long v) {
    float2 r;
    asm("mov.b64 {%0, %1}, %2;" : "=f"(r.x), "=f"(r.y) : "l"(v));
    return r;
}

// ---------------- gemm128 body (shared by merged + standalone kernels) ----------------
struct GemmSmem { float ws[32][132]; float xs[128][36]; };

__device__ __forceinline__ void gemm128_body(GemmSmem& sm,
                                             const float* __restrict__ A,
                                             const float* __restrict__ W,
                                             float* __restrict__ C,
                                             int row0, int t) {
    const int tx = t & 15;
    const int ty = t >> 4;

    unsigned long long acc[8][4];
    #pragma unroll
    for (int r = 0; r < 8; r++)
        #pragma unroll
        for (int p = 0; p < 4; p++) acc[r][p] = 0ULL;

    for (int kc = 0; kc < 128; kc += 32) {
        #pragma unroll
        for (int i = t; i < 1024; i += 256) {
            int r = i >> 5, c4 = i & 31;
            float4 v = *reinterpret_cast<const float4*>(&W[(kc + r) * 128 + c4 * 4]);
            *reinterpret_cast<float4*>(&sm.ws[r][c4 * 4]) = v;
        }
        #pragma unroll
        for (int i = t; i < 1024; i += 256) {
            int r = i >> 3, c4 = i & 7;
            int gr = row0 + r;
            float4 v = make_float4(0.f, 0.f, 0.f, 0.f);
            if (gr < NN) v = *reinterpret_cast<const float4*>(&A[(size_t)gr * 128 + kc + c4 * 4]);
            *reinterpret_cast<float4*>(&sm.xs[r][c4 * 4]) = v;
        }
        __syncthreads();
        #pragma unroll
        for (int k0 = 0; k0 < 32; k0 += 4) {
            float4 xa[8];
            #pragma unroll
            for (int r = 0; r < 8; r++)
                xa[r] = *reinterpret_cast<float4*>(&sm.xs[ty * 8 + r][k0]);
            #pragma unroll
            for (int kk = 0; kk < 4; kk++) {
                const ulonglong2* wp = reinterpret_cast<const ulonglong2*>(&sm.ws[k0 + kk][tx * 8]);
                ulonglong2 wA = wp[0];
                ulonglong2 wB = wp[1];
                #pragma unroll
                for (int r = 0; r < 8; r++) {
                    float a = (kk == 0) ? xa[r].x : (kk == 1) ? xa[r].y
                            : (kk == 2) ? xa[r].z : xa[r].w;
                    unsigned long long aa = pk2(a, a);
                    acc[r][0] = fma2(aa, wA.x, acc[r][0]);
                    acc[r][1] = fma2(aa, wA.y, acc[r][1]);
                    acc[r][2] = fma2(aa, wB.x, acc[r][2]);
                    acc[r][3] = fma2(aa, wB.y, acc[r][3]);
                }
            }
        }
        __syncthreads();
    }
    #pragma unroll
    for (int r = 0; r < 8; r++) {
        int gr = row0 + ty * 8 + r;
        if (gr < NN) {
            float2 p0 = upk(acc[r][0]), p1 = upk(acc[r][1]);
            float2 p2 = upk(acc[r][2]), p3 = upk(acc[r][3]);
            float4 o0 = make_float4(p0.x, p0.y, p1.x, p1.y);
            float4 o1 = make_float4(p2.x, p2.y, p3.x, p3.y);
            *reinterpret_cast<float4*>(&C[(size_t)gr * 128 + tx * 8])     = o0;
            *reinterpret_cast<float4*>(&C[(size_t)gr * 128 + tx * 8 + 4]) = o1;
        }
    }
}

// ---------------- CSR build pieces ----------------
__global__ void zero_deg_kernel() {
    int i = blockIdx.x * blockDim.x + threadIdx.x;
    if (i < NN) g_deg[i] = 0;
}

// merged: gemm1 first half || degree count
__global__ void __launch_bounds__(256, 2) mergedA_kernel(const float* __restrict__ A,
                                                         const float* __restrict__ W,
                                                         float* __restrict__ C,
                                                         const int* __restrict__ dst) {
    __shared__ GemmSmem sm;
    const int t = threadIdx.x;
    if (blockIdx.x < GHALF) {
        gemm128_body(sm, A, W, C, blockIdx.x * 128, t);
    } else {
        int e = (blockIdx.x - GHALF) * 256 + t;
        if (e < EE) atomicAdd(&g_deg[dst[e]], 1);
    }
}

// merged: gemm1 second half || bucket fill
__global__ void __launch_bounds__(256, 2) mergedB_kernel(const float* __restrict__ A,
                                                         const float* __restrict__ W,
                                                         float* __restrict__ C,
                                                         const int* __restrict__ src,
                                                         const int* __restrict__ dst) {
    __shared__ GemmSmem sm;
    const int t = threadIdx.x;
    if (blockIdx.x < GHALF) {
        gemm128_body(sm, A, W, C, (GHALF + blockIdx.x) * 128, t);
    } else {
        int e = (blockIdx.x - GHALF) * 256 + t;
        if (e < EE) {
            int d = dst[e];
            int pos = atomicAdd(&g_cursor[d], 1);
            g_esrc[pos] = src[e];
        }
    }
}

// block partial sums of deg (512 elems per block)
__global__ void __launch_bounds__(512) blocksum_kernel() {
    __shared__ int wsum[16];
    int t = threadIdx.x, lane = t & 31, wid = t >> 5;
    int i = blockIdx.x * 512 + t;
    int v = (i < NN) ? g_deg[i] : 0;
    #pragma unroll
    for (int d = 16; d > 0; d >>= 1)
        v += __shfl_xor_sync(0xFFFFFFFFu, v, d);
    if (lane == 0) wsum[wid] = v;
    __syncthreads();
    if (wid == 0) {
        int s = (lane < 16) ? wsum[lane] : 0;
        #pragma unroll
        for (int d = 8; d > 0; d >>= 1)
            s += __shfl_xor_sync(0xFFFFFFFFu, s, d);
        if (lane == 0) g_bsum[blockIdx.x] = s;
    }
}

// single block scans NBLK partials -> exclusive offsets
__global__ void __launch_bounds__(256) scanpart_kernel() {
    __shared__ int wsum[8];
    int t = threadIdx.x, lane = t & 31, wid = t >> 5;
    int v = (t < NBLK) ? g_bsum[t] : 0;
    int inc = v;
    #pragma unroll
    for (int d = 1; d < 32; d <<= 1) {
        int u = __shfl_up_sync(0xFFFFFFFFu, inc, d);
        if (lane >= d) inc += u;
    }
    if (lane == 31) wsum[wid] = inc;
    __syncthreads();
    if (wid == 0) {
        int s = (lane < 8) ? wsum[lane] : 0;
        int si = s;
        #pragma unroll
        for (int d = 1; d < 8; d <<= 1) {
            int u = __shfl_up_sync(0xFFFFFFFFu, si, d);
            if (lane >= d) si += u;
        }
        if (lane < 8) wsum[lane] = si - s;  // exclusive
    }
    __syncthreads();
    if (t < NBLK) g_boff[t] = wsum[wid] + inc - v;  // exclusive scan
}

// per-block rescan -> rowptr, cursor, dinv (fused)
__global__ void __launch_bounds__(512) rowptr_kernel() {
    __shared__ int wsum[16];
    int t = threadIdx.x, lane = t & 31, wid = t >> 5;
    int i = blockIdx.x * 512 + t;
    int v = (i < NN) ? g_deg[i] : 0;
    int inc = v;
    #pragma unroll
    for (int d = 1; d < 32; d <<= 1) {
        int u = __shfl_up_sync(0xFFFFFFFFu, inc, d);
        if (lane >= d) inc += u;
    }
    if (lane == 31) wsum[wid] = inc;
    __syncthreads();
    if (wid == 0) {
        int s = (lane < 16) ? wsum[lane] : 0;
        int si = s;
        #pragma unroll
        for (int d = 1; d < 16; d <<= 1) {
            int u = __shfl_up_sync(0xFFFFFFFFu, si, d);
            if (lane >= d) si += u;
        }
        if (lane < 16) wsum[lane] = si - s;  // exclusive
    }
    __syncthreads();
    int incl = g_boff[blockIdx.x] + wsum[wid] + inc;
    if (i < NN) {
        g_rowptr[i + 1] = incl;
        g_cursor[i] = incl - v;
        g_dinv[i] = rsqrtf((float)v + 1.0f);
    }
    if (i == 0) g_rowptr[0] = 0;
}

// ---------------- standalone gemm (layer 2) ----------------
__global__ void __launch_bounds__(256, 2) gemm128_kernel(const float* __restrict__ A,
                                                         const float* __restrict__ W,
                                                         float* __restrict__ C) {
    __shared__ GemmSmem sm;
    gemm128_body(sm, A, W, C, blockIdx.x * 128, threadIdx.x);
}

// ---------------- aggregation: one warp per node, shfl-broadcast, f32x2 ----------------
__global__ void __launch_bounds__(256) agg_kernel(const float* __restrict__ hpre,
                                                  const float* __restrict__ bias,
                                                  float* __restrict__ hout) {
    int warp = (blockIdx.x * blockDim.x + threadIdx.x) >> 5;
    int lane = threadIdx.x & 31;
    if (warp >= NN) return;
    const int u = warp;
    const float du = g_dinv[u];

    ulonglong2 self = *reinterpret_cast<const ulonglong2*>(&hpre[(size_t)u * 128 + lane * 4]);
    const unsigned long long selfc = pk2(du * du, du * du);
    ulonglong2 acc;
    acc.x = fma2(self.x, selfc, 0ULL);
    acc.y = fma2(self.y, selfc, 0ULL);

    const int beg = g_rowptr[u], end = g_rowptr[u + 1];
    for (int base = beg; base < end; base += 32) {
        int rem = end - base;
        int n = rem < 32 ? rem : 32;
        int s = 0; float c = 0.f;
        if (lane < n) {
            s = g_esrc[base + lane];
            c = g_dinv[s] * du;
        }
        #pragma unroll 4
        for (int k = 0; k < n; k++) {
            int   sk = __shfl_sync(0xFFFFFFFFu, s, k);
            float ck = __shfl_sync(0xFFFFFFFFu, c, k);
            ulonglong2 hv = __ldg(reinterpret_cast<const ulonglong2*>(&hpre[(size_t)sk * 128]) + lane);
            unsigned long long cc = pk2(ck, ck);
            acc.x = fma2(hv.x, cc, acc.x);
            acc.y = fma2(hv.y, cc, acc.y);
        }
    }
    float4 bb = *reinterpret_cast<const float4*>(&bias[lane * 4]);
    float2 a0 = upk(acc.x), a1 = upk(acc.y);
    float4 o;
    o.x = fmaxf(a0.x + bb.x, 0.f);
    o.y = fmaxf(a0.y + bb.y, 0.f);
    o.z = fmaxf(a1.x + bb.z, 0.f);
    o.w = fmaxf(a1.y + bb.w, 0.f);
    *reinterpret_cast<float4*>(&hout[(size_t)u * 128 + lane * 4]) = o;
}

// ---------------- final: out[N,40] = log_softmax([h1|h2] @ Wlin + blin) ----------------
// 256 rows x 40 cols per block; fused log-softmax via smem logits.
union OutSmem {
    struct { float hs[32][260]; float wl[32][40]; } g;
    float logits[256][41];
};

__global__ void __launch_bounds__(256, 2) gemmout_kernel(const float* __restrict__ h1,
                                                         const float* __restrict__ h2,
                                                         const float* __restrict__ Wlin,
                                                         const float* __restrict__ blin,
                                                         float* __restrict__ out) {
    __shared__ OutSmem sm;
    const int t = threadIdx.x;
    const int cg = t & 7;     // cols cg*5 .. cg*5+4
    const int rg = t >> 3;    // rows rg*8 .. rg*8+7
    const int row0 = blockIdx.x * 256;

    unsigned long long acc[4][5];
    #pragma unroll
    for (int j = 0; j < 4; j++)
        #pragma unroll
        for (int c = 0; c < 5; c++) acc[j][c] = 0ULL;

    for (int kc = 0; kc < 256; kc += 32) {
        const float* hsrc = (kc < 128) ? h1 : h2;
        const int koff = kc & 127;
        #pragma unroll
        for (int i = t; i < 2048; i += 256) {
            int r = i >> 3, k4 = i & 7;
            int gr = row0 + r;
            float4 v = make_float4(0.f, 0.f, 0.f, 0.f);
            if (gr < NN) v = *reinterpret_cast<const float4*>(&hsrc[(size_t)gr * 128 + koff + k4 * 4]);
            sm.g.hs[k4 * 4 + 0][r] = v.x;
            sm.g.hs[k4 * 4 + 1][r] = v.y;
            sm.g.hs[k4 * 4 + 2][r] = v.z;
            sm.g.hs[k4 * 4 + 3][r] = v.w;
        }
        #pragma unroll
        for (int i = t; i < 1280; i += 256) {
            int r = i / 40, c = i % 40;
            sm.g.wl[r][c] = Wlin[(kc + r) * 40 + c];
        }
        __syncthreads();
        #pragma unroll
        for (int k = 0; k < 32; k++) {
            const ulonglong2* xp = reinterpret_cast<const ulonglong2*>(&sm.g.hs[k][rg * 8]);
            ulonglong2 xA = xp[0];
            ulonglong2 xB = xp[1];
            #pragma unroll
            for (int c = 0; c < 5; c++) {
                float w = sm.g.wl[k][cg * 5 + c];
                unsigned long long ww = pk2(w, w);
                acc[0][c] = fma2(xA.x, ww, acc[0][c]);
                acc[1][c] = fma2(xA.y, ww, acc[1][c]);
                acc[2][c] = fma2(xB.x, ww, acc[2][c]);
                acc[3][c] = fma2(xB.y, ww, acc[3][c]);
            }
        }
        __syncthreads();
    }

    // stash logits (+bias) into smem (union reuse; all compute done)
    #pragma unroll
    for (int j = 0; j < 4; j++) {
        int lr = rg * 8 + 2 * j;
        #pragma unroll
        for (int c = 0; c < 5; c++) {
            float2 p = upk(acc[j][c]);
            float b = blin[cg * 5 + c];
            sm.logits[lr][cg * 5 + c]     = p.x + b;
            sm.logits[lr + 1][cg * 5 + c] = p.y + b;
        }
    }
    __syncthreads();

    // per-thread row log-softmax
    int gr = row0 + t;
    if (gr < NN) {
        float m = -INFINITY;
        #pragma unroll
        for (int c = 0; c < 40; c++) m = fmaxf(m, sm.logits[t][c]);
        float s = 0.f;
        #pragma unroll
        for (int c = 0; c < 40; c++) s += expf(sm.logits[t][c] - m);
        float lse = m + logf(s);
        float* po = out + (size_t)gr * 40;
        #pragma unroll
        for (int c = 0; c < 40; c += 4) {
            float4 v = make_float4(sm.logits[t][c]     - lse,
                                   sm.logits[t][c + 1] - lse,
                                   sm.logits[t][c + 2] - lse,
                                   sm.logits[t][c + 3] - lse);
            *reinterpret_cast<float4*>(po + c) = v;
        }
    }
}

// ---------------- launch ----------------
extern "C" void kernel_launch(void* const* d_in, const int* in_sizes, int n_in,
                              void* d_out, int out_size) {
    const float* x    = (const float*)d_in[0];
    const int*   ei   = (const int*)d_in[1];
    const float* W1   = (const float*)d_in[2];
    const float* b1   = (const float*)d_in[3];
    const float* W2   = (const float*)d_in[4];
    const float* b2   = (const float*)d_in[5];
    const float* Wlin = (const float*)d_in[6];
    const float* blin = (const float*)d_in[7];
    float* out = (float*)d_out;

    const int* src = ei;        // edge_index[0]
    const int* dst = ei + EE;   // edge_index[1]

    float *p_hpre, *p_h1, *p_h2;
    cudaGetSymbolAddress((void**)&p_hpre, g_hpre);
    cudaGetSymbolAddress((void**)&p_h1, g_h1);
    cudaGetSymbolAddress((void**)&p_h2, g_h2);

    const int NB_N = (NN + 255) / 256;
    const int NB_W = (NN * 32 + 255) / 256;   // warp-per-node grids
    const int NB_G128 = (NN + 127) / 128;
    const int NB_G256 = (NN + 255) / 256;

    zero_deg_kernel<<<NB_N, 256>>>();
    mergedA_kernel<<<GHALF + NB_E, 256>>>(x, W1, p_hpre, dst);   // gemm1 half1 || count
    blocksum_kernel<<<NBLK, 512>>>();
    scanpart_kernel<<<1, 256>>>();
    rowptr_kernel<<<NBLK, 512>>>();
    mergedB_kernel<<<GHALF + NB_E, 256>>>(x, W1, p_hpre, src, dst);  // gemm1 half2 || fill
    agg_kernel<<<NB_W, 256>>>(p_hpre, b1, p_h1);

    gemm128_kernel<<<NB_G128, 256>>>(p_h1, W2, p_hpre);
    agg_kernel<<<NB_W, 256>>>(p_hpre, b2, p_h2);

    gemmout_kernel<<<NB_G256, 256>>>(p_h1, p_h2, Wlin, blin, out);
}

// round 7
// speedup vs baseline: 1.5381x; 1.0341x over previous
#include <cuda_runtime.h>
#include <cuda_fp16.h>
#include <math.h>

#define NN 100000
#define EE 1600000
#define HH 128
#define CC 40
#define NBLK 196        // ceil(100000/512)
#define GHALF 391       // gemm blocks per half (391*128 = 50048 rows)
#define EB 296          // grid-stride edge blocks per merged kernel

// ---------------- scratch (no allocations allowed) ----------------
__device__ float  g_hpre[NN * HH];
__device__ __half g_hpre16[NN * HH];
__device__ float  g_h1[NN * HH];
__device__ float  g_h2[NN * HH];
__device__ float  g_dinv[NN];
__device__ int    g_deg[NN];          // zero-initialized; invariant: zero at launch entry
__device__ int    g_rowptr[NN + 1];
__device__ int    g_cursor[NN];
__device__ int    g_esrc[EE];
__device__ float  g_ecoef[EE];
__device__ int    g_bsum[NBLK];

// ---------------- f32x2 helpers ----------------
__device__ __forceinline__ unsigned long long fma2(unsigned long long a,
                                                   unsigned long long b,
                                                   unsigned long long c) {
    unsigned long long d;
    asm("fma.rn.f32x2 %0, %1, %2, %3;" : "=l"(d) : "l"(a), "l"(b), "l"(c));
    return d;
}
__device__ __forceinline__ unsigned long long pk2(float lo, float hi) {
    unsigned long long d;
    asm("mov.b64 %0, {%1, %2};" : "=l"(d) : "f"(lo), "f"(hi));
    return d;
}
__device__ __forceinline__ float2 upk(unsigned long long v) {
    float2 r;
    asm("mov.b64 {%0, %1}, %2;" : "=f"(r.x), "=f"(r.y) : "l"(v));
    return r;
}

// ---------------- gemm128 body: C = A@W (fp32) + fp16 shadow ----------------
struct GemmSmem { float ws[32][132]; float xs[128][36]; };

__device__ __forceinline__ void gemm128_body(GemmSmem& sm,
                                             const float* __restrict__ A,
                                             const float* __restrict__ W,
                                             float* __restrict__ C,
                                             __half* __restrict__ C16,
                                             int row0, int t) {
    const int tx = t & 15;
    const int ty = t >> 4;

    unsigned long long acc[8][4];
    #pragma unroll
    for (int r = 0; r < 8; r++)
        #pragma unroll
        for (int p = 0; p < 4; p++) acc[r][p] = 0ULL;

    for (int kc = 0; kc < 128; kc += 32) {
        #pragma unroll
        for (int i = t; i < 1024; i += 256) {
            int r = i >> 5, c4 = i & 31;
            float4 v = *reinterpret_cast<const float4*>(&W[(kc + r) * 128 + c4 * 4]);
            *reinterpret_cast<float4*>(&sm.ws[r][c4 * 4]) = v;
        }
        #pragma unroll
        for (int i = t; i < 1024; i += 256) {
            int r = i >> 3, c4 = i & 7;
            int gr = row0 + r;
            float4 v = make_float4(0.f, 0.f, 0.f, 0.f);
            if (gr < NN) v = *reinterpret_cast<const float4*>(&A[(size_t)gr * 128 + kc + c4 * 4]);
            *reinterpret_cast<float4*>(&sm.xs[r][c4 * 4]) = v;
        }
        __syncthreads();
        #pragma unroll
        for (int k0 = 0; k0 < 32; k0 += 4) {
            float4 xa[8];
            #pragma unroll
            for (int r = 0; r < 8; r++)
                xa[r] = *reinterpret_cast<float4*>(&sm.xs[ty * 8 + r][k0]);
            #pragma unroll
            for (int kk = 0; kk < 4; kk++) {
                const ulonglong2* wp = reinterpret_cast<const ulonglong2*>(&sm.ws[k0 + kk][tx * 8]);
                ulonglong2 wA = wp[0];
                ulonglong2 wB = wp[1];
                #pragma unroll
                for (int r = 0; r < 8; r++) {
                    float a = (kk == 0) ? xa[r].x : (kk == 1) ? xa[r].y
                            : (kk == 2) ? xa[r].z : xa[r].w;
                    unsigned long long aa = pk2(a, a);
                    acc[r][0] = fma2(aa, wA.x, acc[r][0]);
                    acc[r][1] = fma2(aa, wA.y, acc[r][1]);
                    acc[r][2] = fma2(aa, wB.x, acc[r][2]);
                    acc[r][3] = fma2(aa, wB.y, acc[r][3]);
                }
            }
        }
        __syncthreads();
    }
    #pragma unroll
    for (int r = 0; r < 8; r++) {
        int gr = row0 + ty * 8 + r;
        if (gr < NN) {
            float2 p0 = upk(acc[r][0]), p1 = upk(acc[r][1]);
            float2 p2 = upk(acc[r][2]), p3 = upk(acc[r][3]);
            float4 o0 = make_float4(p0.x, p0.y, p1.x, p1.y);
            float4 o1 = make_float4(p2.x, p2.y, p3.x, p3.y);
            *reinterpret_cast<float4*>(&C[(size_t)gr * 128 + tx * 8])     = o0;
            *reinterpret_cast<float4*>(&C[(size_t)gr * 128 + tx * 8 + 4]) = o1;
            // fp16 shadow (8 halfs = 16B)
            __half2 h0 = __float22half2_rn(p0);
            __half2 h1 = __float22half2_rn(p1);
            __half2 h2 = __float22half2_rn(p2);
            __half2 h3 = __float22half2_rn(p3);
            uint4 hraw;
            hraw.x = *reinterpret_cast<unsigned*>(&h0);
            hraw.y = *reinterpret_cast<unsigned*>(&h1);
            hraw.z = *reinterpret_cast<unsigned*>(&h2);
            hraw.w = *reinterpret_cast<unsigned*>(&h3);
            *reinterpret_cast<uint4*>(&C16[(size_t)gr * 128 + tx * 8]) = hraw;
        }
    }
}

// ---------------- merged: gemm1 half1 || degree count (grid-stride) ----------------
__global__ void __launch_bounds__(256, 2) mergedA_kernel(const float* __restrict__ A,
                                                         const float* __restrict__ W,
                                                         float* __restrict__ C,
                                                         __half* __restrict__ C16,
                                                         const int* __restrict__ dst) {
    __shared__ GemmSmem sm;
    const int t = threadIdx.x;
    if (blockIdx.x < GHALF) {
        gemm128_body(sm, A, W, C, C16, blockIdx.x * 128, t);
    } else {
        const int stride = EB * 256;
        for (int e = (blockIdx.x - GHALF) * 256 + t; e < EE; e += stride)
            atomicAdd(&g_deg[dst[e]], 1);
    }
}

// ---------------- merged: gemm1 half2 || bucket fill (esrc + ecoef) ----------------
__global__ void __launch_bounds__(256, 2) mergedB_kernel(const float* __restrict__ A,
                                                         const float* __restrict__ W,
                                                         float* __restrict__ C,
                                                         __half* __restrict__ C16,
                                                         const int* __restrict__ src,
                                                         const int* __restrict__ dst) {
    __shared__ GemmSmem sm;
    const int t = threadIdx.x;
    if (blockIdx.x < GHALF) {
        gemm128_body(sm, A, W, C, C16, (GHALF + blockIdx.x) * 128, t);
    } else {
        const int stride = EB * 256;
        for (int e = (blockIdx.x - GHALF) * 256 + t; e < EE; e += stride) {
            int d = dst[e];
            int s = src[e];
            int pos = atomicAdd(&g_cursor[d], 1);
            g_esrc[pos] = s;
            g_ecoef[pos] = g_dinv[s] * g_dinv[d];
        }
    }
}

// ---------------- block partial sums of deg (512 elems per block) ----------------
__global__ void __launch_bounds__(512) blocksum_kernel() {
    __shared__ int wsum[16];
    int t = threadIdx.x, lane = t & 31, wid = t >> 5;
    int i = blockIdx.x * 512 + t;
    int v = (i < NN) ? g_deg[i] : 0;
    #pragma unroll
    for (int d = 16; d > 0; d >>= 1)
        v += __shfl_xor_sync(0xFFFFFFFFu, v, d);
    if (lane == 0) wsum[wid] = v;
    __syncthreads();
    if (wid == 0) {
        int s = (lane < 16) ? wsum[lane] : 0;
        #pragma unroll
        for (int d = 8; d > 0; d >>= 1)
            s += __shfl_xor_sync(0xFFFFFFFFu, s, d);
        if (lane == 0) g_bsum[blockIdx.x] = s;
    }
}

// ---------------- rowptr: inline bsum prefix + block scan + dinv/cursor; resets deg ----------------
__global__ void __launch_bounds__(512) rowptr_kernel() {
    __shared__ int wsum[16];
    __shared__ int s_base;
    int t = threadIdx.x, lane = t & 31, wid = t >> 5;

    // prefix of bsum[0 .. bid)
    int pre = 0;
    for (int j = t; j < blockIdx.x; j += 512) pre += g_bsum[j];
    #pragma unroll
    for (int d = 16; d > 0; d >>= 1)
        pre += __shfl_xor_sync(0xFFFFFFFFu, pre, d);
    if (lane == 0) wsum[wid] = pre;
    __syncthreads();
    if (t == 0) {
        int b = 0;
        #pragma unroll
        for (int w = 0; w < 16; w++) b += wsum[w];
        s_base = b;
    }
    __syncthreads();
    const int base = s_base;
    __syncthreads();   // wsum reused below

    int i = blockIdx.x * 512 + t;
    int v = (i < NN) ? g_deg[i] : 0;
    int inc = v;
    #pragma unroll
    for (int d = 1; d < 32; d <<= 1) {
        int u = __shfl_up_sync(0xFFFFFFFFu, inc, d);
        if (lane >= d) inc += u;
    }
    if (lane == 31) wsum[wid] = inc;
    __syncthreads();
    if (wid == 0) {
        int s = (lane < 16) ? wsum[lane] : 0;
        int si = s;
        #pragma unroll
        for (int d = 1; d < 16; d <<= 1) {
            int u = __shfl_up_sync(0xFFFFFFFFu, si, d);
            if (lane >= d) si += u;
        }
        if (lane < 16) wsum[lane] = si - s;  // exclusive
    }
    __syncthreads();
    int incl = base + wsum[wid] + inc;
    if (i < NN) {
        g_rowptr[i + 1] = incl;
        g_cursor[i] = incl - v;
        g_dinv[i] = rsqrtf((float)v + 1.0f);
        g_deg[i] = 0;                 // restore invariant for next graph replay
    }
    if (i == 0) g_rowptr[0] = 0;
}

// ---------------- standalone gemm (layer 2) ----------------
__global__ void __launch_bounds__(256, 2) gemm128_kernel(const float* __restrict__ A,
                                                         const float* __restrict__ W,
                                                         float* __restrict__ C,
                                                         __half* __restrict__ C16) {
    __shared__ GemmSmem sm;
    gemm128_body(sm, A, W, C, C16, blockIdx.x * 128, threadIdx.x);
}

// ---------------- aggregation: warp/node, fp16 neighbor gather, fp32 accumulate ----------------
__global__ void __launch_bounds__(256) agg_kernel(const float* __restrict__ hpre,
                                                  const __half* __restrict__ hp16,
                                                  const float* __restrict__ bias,
                                                  float* __restrict__ hout) {
    int warp = (blockIdx.x * blockDim.x + threadIdx.x) >> 5;
    int lane = threadIdx.x & 31;
    if (warp >= NN) return;
    const int u = warp;
    const float du = g_dinv[u];

    ulonglong2 self = *reinterpret_cast<const ulonglong2*>(&hpre[(size_t)u * 128 + lane * 4]);
    const unsigned long long selfc = pk2(du * du, du * du);
    ulonglong2 acc;
    acc.x = fma2(self.x, selfc, 0ULL);
    acc.y = fma2(self.y, selfc, 0ULL);

    const int beg = g_rowptr[u], end = g_rowptr[u + 1];
    for (int base = beg; base < end; base += 32) {
        int rem = end - base;
        int n = rem < 32 ? rem : 32;
        int s = 0; float c = 0.f;
        if (lane < n) {
            s = g_esrc[base + lane];
            c = g_ecoef[base + lane];
        }
        #pragma unroll 4
        for (int k = 0; k < n; k++) {
            int   sk = __shfl_sync(0xFFFFFFFFu, s, k);
            float ck = __shfl_sync(0xFFFFFFFFu, c, k);
            uint2 raw = __ldg(reinterpret_cast<const uint2*>(hp16 + (size_t)sk * 128) + lane);
            __half2 hlo = *reinterpret_cast<__half2*>(&raw.x);
            __half2 hhi = *reinterpret_cast<__half2*>(&raw.y);
            float2 f0 = __half22float2(hlo);
            float2 f1 = __half22float2(hhi);
            unsigned long long cc = pk2(ck, ck);
            acc.x = fma2(pk2(f0.x, f0.y), cc, acc.x);
            acc.y = fma2(pk2(f1.x, f1.y), cc, acc.y);
        }
    }
    float4 bb = *reinterpret_cast<const float4*>(&bias[lane * 4]);
    float2 a0 = upk(acc.x), a1 = upk(acc.y);
    float4 o;
    o.x = fmaxf(a0.x + bb.x, 0.f);
    o.y = fmaxf(a0.y + bb.y, 0.f);
    o.z = fmaxf(a1.x + bb.z, 0.f);
    o.w = fmaxf(a1.y + bb.w, 0.f);
    *reinterpret_cast<float4*>(&hout[(size_t)u * 128 + lane * 4]) = o;
}

// ---------------- final: out[N,40] = log_softmax([h1|h2] @ Wlin + blin) ----------------
union OutSmem {
    struct { float hs[32][260]; float wl[32][40]; } g;
    float logits[256][41];
};

__global__ void __launch_bounds__(256, 2) gemmout_kernel(const float* __restrict__ h1,
                                                         const float* __restrict__ h2,
                                                         const float* __restrict__ Wlin,
                                                         const float* __restrict__ blin,
                                                         float* __restrict__ out) {
    __shared__ OutSmem sm;
    const int t = threadIdx.x;
    const int cg = t & 7;
    const int rg = t >> 3;
    const int row0 = blockIdx.x * 256;

    unsigned long long acc[4][5];
    #pragma unroll
    for (int j = 0; j < 4; j++)
        #pragma unroll
        for (int c = 0; c < 5; c++) acc[j][c] = 0ULL;

    for (int kc = 0; kc < 256; kc += 32) {
        const float* hsrc = (kc < 128) ? h1 : h2;
        const int koff = kc & 127;
        #pragma unroll
        for (int i = t; i < 2048; i += 256) {
            int r = i >> 3, k4 = i & 7;
            int gr = row0 + r;
            float4 v = make_float4(0.f, 0.f, 0.f, 0.f);
            if (gr < NN) v = *reinterpret_cast<const float4*>(&hsrc[(size_t)gr * 128 + koff + k4 * 4]);
            sm.g.hs[k4 * 4 + 0][r] = v.x;
            sm.g.hs[k4 * 4 + 1][r] = v.y;
            sm.g.hs[k4 * 4 + 2][r] = v.z;
            sm.g.hs[k4 * 4 + 3][r] = v.w;
        }
        #pragma unroll
        for (int i = t; i < 1280; i += 256) {
            int r = i / 40, c = i % 40;
            sm.g.wl[r][c] = Wlin[(kc + r) * 40 + c];
        }
        __syncthreads();
        #pragma unroll
        for (int k = 0; k < 32; k++) {
            const ulonglong2* xp = reinterpret_cast<const ulonglong2*>(&sm.g.hs[k][rg * 8]);
            ulonglong2 xA = xp[0];
            ulonglong2 xB = xp[1];
            #pragma unroll
            for (int c = 0; c < 5; c++) {
                float w = sm.g.wl[k][cg * 5 + c];
                unsigned long long ww = pk2(w, w);
                acc[0][c] = fma2(xA.x, ww, acc[0][c]);
                acc[1][c] = fma2(xA.y, ww, acc[1][c]);
                acc[2][c] = fma2(xB.x, ww, acc[2][c]);
                acc[3][c] = fma2(xB.y, ww, acc[3][c]);
            }
        }
        __syncthreads();
    }

    #pragma unroll
    for (int j = 0; j < 4; j++) {
        int lr = rg * 8 + 2 * j;
        #pragma unroll
        for (int c = 0; c < 5; c++) {
            float2 p = upk(acc[j][c]);
            float b = blin[cg * 5 + c];
            sm.logits[lr][cg * 5 + c]     = p.x + b;
            sm.logits[lr + 1][cg * 5 + c] = p.y + b;
        }
    }
    __syncthreads();

    int gr = row0 + t;
    if (gr < NN) {
        float m = -INFINITY;
        #pragma unroll
        for (int c = 0; c < 40; c++) m = fmaxf(m, sm.logits[t][c]);
        float s = 0.f;
        #pragma unroll
        for (int c = 0; c < 40; c++) s += expf(sm.logits[t][c] - m);
        float lse = m + logf(s);
        float* po = out + (size_t)gr * 40;
        #pragma unroll
        for (int c = 0; c < 40; c += 4) {
            float4 v = make_float4(sm.logits[t][c]     - lse,
                                   sm.logits[t][c + 1] - lse,
                                   sm.logits[t][c + 2] - lse,
                                   sm.logits[t][c + 3] - lse);
            *reinterpret_cast<float4*>(po + c) = v;
        }
    }
}

// ---------------- launch ----------------
extern "C" void kernel_launch(void* const* d_in, const int* in_sizes, int n_in,
                              void* d_out, int out_size) {
    const float* x    = (const float*)d_in[0];
    const int*   ei   = (const int*)d_in[1];
    const float* W1   = (const float*)d_in[2];
    const float* b1   = (const float*)d_in[3];
    const float* W2   = (const float*)d_in[4];
    const float* b2   = (const float*)d_in[5];
    const float* Wlin = (const float*)d_in[6];
    const float* blin = (const float*)d_in[7];
    float* out = (float*)d_out;

    const int* src = ei;        // edge_index[0]
    const int* dst = ei + EE;   // edge_index[1]

    float *p_hpre, *p_h1, *p_h2;
    __half* p_hpre16;
    cudaGetSymbolAddress((void**)&p_hpre, g_hpre);
    cudaGetSymbolAddress((void**)&p_hpre16, g_hpre16);
    cudaGetSymbolAddress((void**)&p_h1, g_h1);
    cudaGetSymbolAddress((void**)&p_h2, g_h2);

    const int NB_W = (NN * 32 + 255) / 256;   // warp-per-node grids
    const int NB_G128 = (NN + 127) / 128;
    const int NB_G256 = (NN + 255) / 256;

    mergedA_kernel<<<GHALF + EB, 256>>>(x, W1, p_hpre, p_hpre16, dst);      // 1
    blocksum_kernel<<<NBLK, 512>>>();                                        // 2
    rowptr_kernel<<<NBLK, 512>>>();                                          // 3
    mergedB_kernel<<<GHALF + EB, 256>>>(x, W1, p_hpre, p_hpre16, src, dst);  // 4 (ncu target)
    agg_kernel<<<NB_W, 256>>>(p_hpre, p_hpre16, b1, p_h1);                   // 5
    gemm128_kernel<<<NB_G128, 256>>>(p_h1, W2, p_hpre, p_hpre16);            // 6
    agg_kernel<<<NB_W, 256>>>(p_hpre, p_hpre16, b2, p_h2);                   // 7
    gemmout_kernel<<<NB_G256, 256>>>(p_h1, p_h2, Wlin, blin, out);           // 8
}

// round 8
// speedup vs baseline: 2.3243x; 1.5111x over previous
#include <cuda_runtime.h>
#include <cuda_fp16.h>
#include <math.h>

#define NN 100000
#define EE 1600000
#define HH 128
#define CC 40
#define NBLK 196        // ceil(100000/512)
#define GHALF 391       // gemm row-tiles per half (391*128 = 50048 rows)
#define GFULL 782       // ceil(100000/128)
#define EB 296          // grid-stride edge blocks per merged kernel

// ---------------- scratch (no allocations allowed) ----------------
__device__ __half g_hpre16[NN * HH];
__device__ __half g_h116[NN * HH];
__device__ __half g_h216[NN * HH];
__device__ float  g_dinv[NN];
__device__ int    g_deg[NN];          // invariant: zero at launch entry
__device__ int    g_rowptr[NN + 1];
__device__ int    g_cursor[NN];
__device__ int    g_esrc[EE];
__device__ float  g_ecoef[EE];
__device__ int    g_bsum[NBLK];

// ---------------- f32x2 helpers ----------------
__device__ __forceinline__ unsigned long long fma2(unsigned long long a,
                                                   unsigned long long b,
                                                   unsigned long long c) {
    unsigned long long d;
    asm("fma.rn.f32x2 %0, %1, %2, %3;" : "=l"(d) : "l"(a), "l"(b), "l"(c));
    return d;
}
__device__ __forceinline__ unsigned long long pk2(float lo, float hi) {
    unsigned long long d;
    asm("mov.b64 %0, {%1, %2};" : "=l"(d) : "f"(lo), "f"(hi));
    return d;
}
__device__ __forceinline__ float2 upk(unsigned long long v) {
    float2 r;
    asm("mov.b64 {%0, %1}, %2;" : "=f"(r.x), "=f"(r.y) : "l"(v));
    return r;
}

// ---------------- HMMA helpers ----------------
__device__ __forceinline__ void ldsm_x4(unsigned& r0, unsigned& r1, unsigned& r2, unsigned& r3,
                                        const void* p) {
    unsigned addr = (unsigned)__cvta_generic_to_shared(p);
    asm volatile("ldmatrix.sync.aligned.m8n8.x4.shared.b16 {%0,%1,%2,%3}, [%4];"
                 : "=r"(r0), "=r"(r1), "=r"(r2), "=r"(r3) : "r"(addr));
}
__device__ __forceinline__ void ldsm_x4_t(unsigned& r0, unsigned& r1, unsigned& r2, unsigned& r3,
                                          const void* p) {
    unsigned addr = (unsigned)__cvta_generic_to_shared(p);
    asm volatile("ldmatrix.sync.aligned.m8n8.x4.trans.shared.b16 {%0,%1,%2,%3}, [%4];"
                 : "=r"(r0), "=r"(r1), "=r"(r2), "=r"(r3) : "r"(addr));
}
__device__ __forceinline__ void mma16816(float* d, const unsigned* a, unsigned b0, unsigned b1) {
    asm volatile("mma.sync.aligned.m16n8k16.row.col.f32.f16.f16.f32 "
                 "{%0,%1,%2,%3}, {%4,%5,%6,%7}, {%8,%9}, {%0,%1,%2,%3};"
                 : "+f"(d[0]), "+f"(d[1]), "+f"(d[2]), "+f"(d[3])
                 : "r"(a[0]), "r"(a[1]), "r"(a[2]), "r"(a[3]), "r"(b0), "r"(b1));
}

// ---------------- HMMA gemm body: C16[rows,128] = A[rows,128] @ W[128,128] ----------------
// block: 128-row tile, 256 threads = 8 warps (4 m-warps x 2 n-warps; warp = 32 rows x 64 cols)
struct HSmem { __half a[128][72]; __half w[64][136]; };  // 35.8 KB

template <bool F16IN>
__device__ __forceinline__ void gemm_hmma_body(HSmem& sm,
                                               const void* __restrict__ Ap,
                                               const float* __restrict__ W,
                                               __half* __restrict__ C16,
                                               int row0, int t) {
    const int lane = t & 31, wid = t >> 5;
    const int wm = wid & 3;        // m-warp: rows wm*32
    const int wn = wid >> 2;       // n-warp: cols wn*64

    float d[2][8][4];
    #pragma unroll
    for (int mi = 0; mi < 2; mi++)
        #pragma unroll
        for (int ni = 0; ni < 8; ni++)
            #pragma unroll
            for (int p = 0; p < 4; p++) d[mi][ni][p] = 0.f;

    for (int kc = 0; kc < 128; kc += 64) {
        // stage A chunk [128 rows][64 k] as fp16
        #pragma unroll
        for (int i = t; i < 2048; i += 256) {
            int r = i >> 4, c4 = i & 15;
            int gr = row0 + r;
            if (F16IN) {
                uint2 raw = make_uint2(0u, 0u);
                if (gr < NN)
                    raw = *reinterpret_cast<const uint2*>(
                        (const __half*)Ap + (size_t)gr * 128 + kc + c4 * 4);
                *reinterpret_cast<uint2*>(&sm.a[r][c4 * 4]) = raw;
            } else {
                float4 v = make_float4(0.f, 0.f, 0.f, 0.f);
                if (gr < NN)
                    v = *reinterpret_cast<const float4*>(
                        (const float*)Ap + (size_t)gr * 128 + kc + c4 * 4);
                __half2 h01 = __floats2half2_rn(v.x, v.y);
                __half2 h23 = __floats2half2_rn(v.z, v.w);
                uint2 raw;
                raw.x = *reinterpret_cast<unsigned*>(&h01);
                raw.y = *reinterpret_cast<unsigned*>(&h23);
                *reinterpret_cast<uint2*>(&sm.a[r][c4 * 4]) = raw;
            }
        }
        // stage W chunk [64 k][128 n] as fp16
        #pragma unroll
        for (int i = t; i < 2048; i += 256) {
            int r = i >> 5, c4 = i & 31;
            float4 v = *reinterpret_cast<const float4*>(&W[(size_t)(kc + r) * 128 + c4 * 4]);
            __half2 h01 = __floats2half2_rn(v.x, v.y);
            __half2 h23 = __floats2half2_rn(v.z, v.w);
            uint2 raw;
            raw.x = *reinterpret_cast<unsigned*>(&h01);
            raw.y = *reinterpret_cast<unsigned*>(&h23);
            *reinterpret_cast<uint2*>(&sm.w[r][c4 * 4]) = raw;
        }
        __syncthreads();

        #pragma unroll
        for (int ks = 0; ks < 4; ks++) {
            const int k0 = ks * 16;
            unsigned a0[4], a1[4];
            // A m16k16 frags: matrices (m_lo,k_lo),(m_hi,k_lo),(m_lo,k_hi),(m_hi,k_hi)
            ldsm_x4(a0[0], a0[1], a0[2], a0[3],
                    &sm.a[wm * 32 + (lane & 15)][k0 + ((lane >> 4) & 1) * 8]);
            ldsm_x4(a1[0], a1[1], a1[2], a1[3],
                    &sm.a[wm * 32 + 16 + (lane & 15)][k0 + ((lane >> 4) & 1) * 8]);
            #pragma unroll
            for (int np = 0; np < 4; np++) {
                unsigned b[4];
                // B k16n8 frag pairs from row-major [k][n] via trans
                ldsm_x4_t(b[0], b[1], b[2], b[3],
                          &sm.w[k0 + (lane & 7) + ((lane >> 3) & 1) * 8]
                               [wn * 64 + np * 16 + (lane >> 4) * 8]);
                mma16816(d[0][2 * np],     a0, b[0], b[1]);
                mma16816(d[0][2 * np + 1], a0, b[2], b[3]);
                mma16816(d[1][2 * np],     a1, b[0], b[1]);
                mma16816(d[1][2 * np + 1], a1, b[2], b[3]);
            }
        }
        __syncthreads();
    }

    // epilogue: fp16 store
    #pragma unroll
    for (int mi = 0; mi < 2; mi++) {
        int row = row0 + wm * 32 + mi * 16 + (lane >> 2);
        #pragma unroll
        for (int ni = 0; ni < 8; ni++) {
            int col = wn * 64 + ni * 8 + (lane & 3) * 2;
            if (row < NN) {
                __half2 h = __floats2half2_rn(d[mi][ni][0], d[mi][ni][1]);
                *reinterpret_cast<__half2*>(&C16[(size_t)row * 128 + col]) = h;
            }
            if (row + 8 < NN) {
                __half2 h = __floats2half2_rn(d[mi][ni][2], d[mi][ni][3]);
                *reinterpret_cast<__half2*>(&C16[(size_t)(row + 8) * 128 + col]) = h;
            }
        }
    }
}

// ---------------- merged: gemm1 half1 || degree count ----------------
__global__ void __launch_bounds__(256) mergedA_kernel(const float* __restrict__ A,
                                                      const float* __restrict__ W,
                                                      __half* __restrict__ C16,
                                                      const int* __restrict__ dst) {
    __shared__ HSmem sm;
    const int t = threadIdx.x;
    if (blockIdx.x < GHALF) {
        gemm_hmma_body<false>(sm, A, W, C16, blockIdx.x * 128, t);
    } else {
        const int stride = EB * 256;
        for (int e = (blockIdx.x - GHALF) * 256 + t; e < EE; e += stride)
            atomicAdd(&g_deg[dst[e]], 1);
    }
}

// ---------------- merged: gemm1 half2 || bucket fill ----------------
__global__ void __launch_bounds__(256) mergedB_kernel(const float* __restrict__ A,
                                                      const float* __restrict__ W,
                                                      __half* __restrict__ C16,
                                                      const int* __restrict__ src,
                                                      const int* __restrict__ dst) {
    __shared__ HSmem sm;
    const int t = threadIdx.x;
    if (blockIdx.x < GHALF) {
        gemm_hmma_body<false>(sm, A, W, C16, (GHALF + blockIdx.x) * 128, t);
    } else {
        const int stride = EB * 256;
        for (int e = (blockIdx.x - GHALF) * 256 + t; e < EE; e += stride) {
            int d = dst[e];
            int s = src[e];
            int pos = atomicAdd(&g_cursor[d], 1);
            g_esrc[pos] = s;
            g_ecoef[pos] = g_dinv[s] * g_dinv[d];
        }
    }
}

// ---------------- standalone gemm layer 2 (fp16 input) ----------------
__global__ void __launch_bounds__(256) gemm16_kernel(const __half* __restrict__ A16,
                                                     const float* __restrict__ W,
                                                     __half* __restrict__ C16) {
    __shared__ HSmem sm;
    gemm_hmma_body<true>(sm, A16, W, C16, blockIdx.x * 128, threadIdx.x);
}

// ---------------- block partial sums of deg ----------------
__global__ void __launch_bounds__(512) blocksum_kernel() {
    __shared__ int wsum[16];
    int t = threadIdx.x, lane = t & 31, wid = t >> 5;
    int i = blockIdx.x * 512 + t;
    int v = (i < NN) ? g_deg[i] : 0;
    #pragma unroll
    for (int d = 16; d > 0; d >>= 1)
        v += __shfl_xor_sync(0xFFFFFFFFu, v, d);
    if (lane == 0) wsum[wid] = v;
    __syncthreads();
    if (wid == 0) {
        int s = (lane < 16) ? wsum[lane] : 0;
        #pragma unroll
        for (int d = 8; d > 0; d >>= 1)
            s += __shfl_xor_sync(0xFFFFFFFFu, s, d);
        if (lane == 0) g_bsum[blockIdx.x] = s;
    }
}

// ---------------- rowptr: bsum prefix + block scan + dinv/cursor; resets deg ----------------
__global__ void __launch_bounds__(512) rowptr_kernel() {
    __shared__ int wsum[16];
    __shared__ int s_base;
    int t = threadIdx.x, lane = t & 31, wid = t >> 5;

    int pre = 0;
    for (int j = t; j < blockIdx.x; j += 512) pre += g_bsum[j];
    #pragma unroll
    for (int d = 16; d > 0; d >>= 1)
        pre += __shfl_xor_sync(0xFFFFFFFFu, pre, d);
    if (lane == 0) wsum[wid] = pre;
    __syncthreads();
    if (t == 0) {
        int b = 0;
        #pragma unroll
        for (int w = 0; w < 16; w++) b += wsum[w];
        s_base = b;
    }
    __syncthreads();
    const int base = s_base;
    __syncthreads();

    int i = blockIdx.x * 512 + t;
    int v = (i < NN) ? g_deg[i] : 0;
    int inc = v;
    #pragma unroll
    for (int d = 1; d < 32; d <<= 1) {
        int u = __shfl_up_sync(0xFFFFFFFFu, inc, d);
        if (lane >= d) inc += u;
    }
    if (lane == 31) wsum[wid] = inc;
    __syncthreads();
    if (wid == 0) {
        int s = (lane < 16) ? wsum[lane] : 0;
        int si = s;
        #pragma unroll
        for (int d = 1; d < 16; d <<= 1) {
            int u = __shfl_up_sync(0xFFFFFFFFu, si, d);
            if (lane >= d) si += u;
        }
        if (lane < 16) wsum[lane] = si - s;
    }
    __syncthreads();
    int incl = base + wsum[wid] + inc;
    if (i < NN) {
        g_rowptr[i + 1] = incl;
        g_cursor[i] = incl - v;
        g_dinv[i] = rsqrtf((float)v + 1.0f);
        g_deg[i] = 0;
    }
    if (i == 0) g_rowptr[0] = 0;
}

// ---------------- aggregation: warp/node, fp16 in/out, fp32 accumulate ----------------
__global__ void __launch_bounds__(256) agg_kernel(const __half* __restrict__ hp16,
                                                  const float* __restrict__ bias,
                                                  __half* __restrict__ hout16) {
    int warp = (blockIdx.x * blockDim.x + threadIdx.x) >> 5;
    int lane = threadIdx.x & 31;
    if (warp >= NN) return;
    const int u = warp;
    const float du = g_dinv[u];

    uint2 sraw = *reinterpret_cast<const uint2*>(hp16 + (size_t)u * 128 + lane * 4);
    float2 s0 = __half22float2(*reinterpret_cast<__half2*>(&sraw.x));
    float2 s1 = __half22float2(*reinterpret_cast<__half2*>(&sraw.y));
    const unsigned long long selfc = pk2(du * du, du * du);
    ulonglong2 acc;
    acc.x = fma2(pk2(s0.x, s0.y), selfc, 0ULL);
    acc.y = fma2(pk2(s1.x, s1.y), selfc, 0ULL);

    const int beg = g_rowptr[u], end = g_rowptr[u + 1];
    for (int base = beg; base < end; base += 32) {
        int rem = end - base;
        int n = rem < 32 ? rem : 32;
        int s = 0; float c = 0.f;
        if (lane < n) {
            s = g_esrc[base + lane];
            c = g_ecoef[base + lane];
        }
        #pragma unroll 8
        for (int k = 0; k < n; k++) {
            int   sk = __shfl_sync(0xFFFFFFFFu, s, k);
            float ck = __shfl_sync(0xFFFFFFFFu, c, k);
            uint2 raw = __ldg(reinterpret_cast<const uint2*>(hp16 + (size_t)sk * 128) + lane);
            float2 f0 = __half22float2(*reinterpret_cast<__half2*>(&raw.x));
            float2 f1 = __half22float2(*reinterpret_cast<__half2*>(&raw.y));
            unsigned long long cc = pk2(ck, ck);
            acc.x = fma2(pk2(f0.x, f0.y), cc, acc.x);
            acc.y = fma2(pk2(f1.x, f1.y), cc, acc.y);
        }
    }
    float4 bb = *reinterpret_cast<const float4*>(&bias[lane * 4]);
    float2 a0 = upk(acc.x), a1 = upk(acc.y);
    __half2 o0 = __floats2half2_rn(fmaxf(a0.x + bb.x, 0.f), fmaxf(a0.y + bb.y, 0.f));
    __half2 o1 = __floats2half2_rn(fmaxf(a1.x + bb.z, 0.f), fmaxf(a1.y + bb.w, 0.f));
    uint2 oraw;
    oraw.x = *reinterpret_cast<unsigned*>(&o0);
    oraw.y = *reinterpret_cast<unsigned*>(&o1);
    *reinterpret_cast<uint2*>(hout16 + (size_t)u * 128 + lane * 4) = oraw;
}

// ---------------- final: out[N,40] = log_softmax([h1|h2] @ Wlin + blin) ----------------
union OutSmem {
    struct { float hs[32][260]; float wl[32][40]; } g;
    float logits[256][41];
};

__global__ void __launch_bounds__(256, 2) gemmout_kernel(const __half* __restrict__ h1,
                                                         const __half* __restrict__ h2,
                                                         const float* __restrict__ Wlin,
                                                         const float* __restrict__ blin,
                                                         float* __restrict__ out) {
    __shared__ OutSmem sm;
    const int t = threadIdx.x;
    const int cg = t & 7;
    const int rg = t >> 3;
    const int row0 = blockIdx.x * 256;

    unsigned long long acc[4][5];
    #pragma unroll
    for (int j = 0; j < 4; j++)
        #pragma unroll
        for (int c = 0; c < 5; c++) acc[j][c] = 0ULL;

    for (int kc = 0; kc < 256; kc += 32) {
        const __half* hsrc = (kc < 128) ? h1 : h2;
        const int koff = kc & 127;
        #pragma unroll
        for (int i = t; i < 2048; i += 256) {
            int r = i >> 3, k4 = i & 7;
            int gr = row0 + r;
            uint2 raw = make_uint2(0u, 0u);
            if (gr < NN)
                raw = *reinterpret_cast<const uint2*>(&hsrc[(size_t)gr * 128 + koff + k4 * 4]);
            float2 f0 = __half22float2(*reinterpret_cast<__half2*>(&raw.x));
            float2 f1 = __half22float2(*reinterpret_cast<__half2*>(&raw.y));
            sm.g.hs[k4 * 4 + 0][r] = f0.x;
            sm.g.hs[k4 * 4 + 1][r] = f0.y;
            sm.g.hs[k4 * 4 + 2][r] = f1.x;
            sm.g.hs[k4 * 4 + 3][r] = f1.y;
        }
        #pragma unroll
        for (int i = t; i < 1280; i += 256) {
            int r = i / 40, c = i % 40;
            sm.g.wl[r][c] = Wlin[(kc + r) * 40 + c];
        }
        __syncthreads();
        #pragma unroll
        for (int k = 0; k < 32; k++) {
            const ulonglong2* xp = reinterpret_cast<const ulonglong2*>(&sm.g.hs[k][rg * 8]);
            ulonglong2 xA = xp[0];
            ulonglong2 xB = xp[1];
            #pragma unroll
            for (int c = 0; c < 5; c++) {
                float w = sm.g.wl[k][cg * 5 + c];
                unsigned long long ww = pk2(w, w);
                acc[0][c] = fma2(xA.x, ww, acc[0][c]);
                acc[1][c] = fma2(xA.y, ww, acc[1][c]);
                acc[2][c] = fma2(xB.x, ww, acc[2][c]);
                acc[3][c] = fma2(xB.y, ww, acc[3][c]);
            }
        }
        __syncthreads();
    }

    #pragma unroll
    for (int j = 0; j < 4; j++) {
        int lr = rg * 8 + 2 * j;
        #pragma unroll
        for (int c = 0; c < 5; c++) {
            float2 p = upk(acc[j][c]);
            float b = blin[cg * 5 + c];
            sm.logits[lr][cg * 5 + c]     = p.x + b;
            sm.logits[lr + 1][cg * 5 + c] = p.y + b;
        }
    }
    __syncthreads();

    int gr = row0 + t;
    if (gr < NN) {
        float m = -INFINITY;
        #pragma unroll
        for (int c = 0; c < 40; c++) m = fmaxf(m, sm.logits[t][c]);
        float s = 0.f;
        #pragma unroll
        for (int c = 0; c < 40; c++) s += expf(sm.logits[t][c] - m);
        float lse = m + logf(s);
        float* po = out + (size_t)gr * 40;
        #pragma unroll
        for (int c = 0; c < 40; c += 4) {
            float4 v = make_float4(sm.logits[t][c]     - lse,
                                   sm.logits[t][c + 1] - lse,
                                   sm.logits[t][c + 2] - lse,
                                   sm.logits[t][c + 3] - lse);
            *reinterpret_cast<float4*>(po + c) = v;
        }
    }
}

// ---------------- launch ----------------
extern "C" void kernel_launch(void* const* d_in, const int* in_sizes, int n_in,
                              void* d_out, int out_size) {
    const float* x    = (const float*)d_in[0];
    const int*   ei   = (const int*)d_in[1];
    const float* W1   = (const float*)d_in[2];
    const float* b1   = (const float*)d_in[3];
    const float* W2   = (const float*)d_in[4];
    const float* b2   = (const float*)d_in[5];
    const float* Wlin = (const float*)d_in[6];
    const float* blin = (const float*)d_in[7];
    float* out = (float*)d_out;

    const int* src = ei;        // edge_index[0]
    const int* dst = ei + EE;   // edge_index[1]

    __half *p_hpre16, *p_h116, *p_h216;
    cudaGetSymbolAddress((void**)&p_hpre16, g_hpre16);
    cudaGetSymbolAddress((void**)&p_h116, g_h116);
    cudaGetSymbolAddress((void**)&p_h216, g_h216);

    const int NB_W = (NN * 32 + 255) / 256;   // warp-per-node grids
    const int NB_G256 = (NN + 255) / 256;

    mergedA_kernel<<<GHALF + EB, 256>>>(x, W1, p_hpre16, dst);               // 1
    blocksum_kernel<<<NBLK, 512>>>();                                         // 2
    rowptr_kernel<<<NBLK, 512>>>();                                           // 3
    mergedB_kernel<<<GHALF + EB, 256>>>(x, W1, p_hpre16, src, dst);           // 4 (ncu target)
    agg_kernel<<<NB_W, 256>>>(p_hpre16, b1, p_h116);                          // 5
    gemm16_kernel<<<GFULL, 256>>>(p_h116, W2, p_hpre16);                      // 6
    agg_kernel<<<NB_W, 256>>>(p_hpre16, b2, p_h216);                          // 7
    gemmout_kernel<<<NB_G256, 256>>>(p_h116, p_h216, Wlin, blin, out);        // 8
}

// round 9
// speedup vs baseline: 2.7776x; 1.1950x over previous
#include <cuda_runtime.h>
#include <cuda_fp16.h>
#include <math.h>

#define NN 100000
#define EE 1600000
#define HH 128
#define CC 40
#define NBLK 196        // ceil(100000/512)
#define GFULL 782       // ceil(100000/128)
#define NB_E 6250       // ceil(EE/256)

// ---------------- scratch (no allocations allowed) ----------------
__device__ __half g_hpre16[NN * HH];
__device__ __half g_h116[NN * HH];
__device__ __half g_h216[NN * HH];
__device__ float  g_dinv[NN];
__device__ int    g_deg[NN];          // invariant: zero at launch entry
__device__ int    g_rowptr[NN + 1];
__device__ int    g_cursor[NN];
__device__ int2   g_epack[EE];        // (src, __float_as_int(coef))
__device__ int    g_bsum[NBLK];

// ---------------- f32x2 helpers ----------------
__device__ __forceinline__ unsigned long long fma2(unsigned long long a,
                                                   unsigned long long b,
                                                   unsigned long long c) {
    unsigned long long d;
    asm("fma.rn.f32x2 %0, %1, %2, %3;" : "=l"(d) : "l"(a), "l"(b), "l"(c));
    return d;
}
__device__ __forceinline__ unsigned long long pk2(float lo, float hi) {
    unsigned long long d;
    asm("mov.b64 %0, {%1, %2};" : "=l"(d) : "f"(lo), "f"(hi));
    return d;
}
__device__ __forceinline__ float2 upk(unsigned long long v) {
    float2 r;
    asm("mov.b64 {%0, %1}, %2;" : "=f"(r.x), "=f"(r.y) : "l"(v));
    return r;
}

// ---------------- HMMA helpers ----------------
__device__ __forceinline__ void ldsm_x4(unsigned& r0, unsigned& r1, unsigned& r2, unsigned& r3,
                                        const void* p) {
    unsigned addr = (unsigned)__cvta_generic_to_shared(p);
    asm volatile("ldmatrix.sync.aligned.m8n8.x4.shared.b16 {%0,%1,%2,%3}, [%4];"
                 : "=r"(r0), "=r"(r1), "=r"(r2), "=r"(r3) : "r"(addr));
}
__device__ __forceinline__ void ldsm_x4_t(unsigned& r0, unsigned& r1, unsigned& r2, unsigned& r3,
                                          const void* p) {
    unsigned addr = (unsigned)__cvta_generic_to_shared(p);
    asm volatile("ldmatrix.sync.aligned.m8n8.x4.trans.shared.b16 {%0,%1,%2,%3}, [%4];"
                 : "=r"(r0), "=r"(r1), "=r"(r2), "=r"(r3) : "r"(addr));
}
__device__ __forceinline__ void mma16816(float* d, const unsigned* a, unsigned b0, unsigned b1) {
    asm volatile("mma.sync.aligned.m16n8k16.row.col.f32.f16.f16.f32 "
                 "{%0,%1,%2,%3}, {%4,%5,%6,%7}, {%8,%9}, {%0,%1,%2,%3};"
                 : "+f"(d[0]), "+f"(d[1]), "+f"(d[2]), "+f"(d[3])
                 : "r"(a[0]), "r"(a[1]), "r"(a[2]), "r"(a[3]), "r"(b0), "r"(b1));
}

// ---------------- HMMA gemm body: C16[rows,128] = A[rows,128] @ W[128,128] ----------------
// block: 128-row tile, 256 threads = 8 warps (4 m-warps x 2 n-warps; warp = 32 rows x 64 cols)
struct HSmem { __half a[128][72]; __half w[64][136]; };

template <bool F16IN>
__device__ __forceinline__ void gemm_hmma_body(HSmem& sm,
                                               const void* __restrict__ Ap,
                                               const float* __restrict__ W,
                                               __half* __restrict__ C16,
                                               int row0, int t) {
    const int lane = t & 31, wid = t >> 5;
    const int wm = wid & 3;
    const int wn = wid >> 2;

    float d[2][8][4];
    #pragma unroll
    for (int mi = 0; mi < 2; mi++)
        #pragma unroll
        for (int ni = 0; ni < 8; ni++)
            #pragma unroll
            for (int p = 0; p < 4; p++) d[mi][ni][p] = 0.f;

    for (int kc = 0; kc < 128; kc += 64) {
        #pragma unroll
        for (int i = t; i < 2048; i += 256) {
            int r = i >> 4, c4 = i & 15;
            int gr = row0 + r;
            if (F16IN) {
                uint2 raw = make_uint2(0u, 0u);
                if (gr < NN)
                    raw = *reinterpret_cast<const uint2*>(
                        (const __half*)Ap + (size_t)gr * 128 + kc + c4 * 4);
                *reinterpret_cast<uint2*>(&sm.a[r][c4 * 4]) = raw;
            } else {
                float4 v = make_float4(0.f, 0.f, 0.f, 0.f);
                if (gr < NN)
                    v = *reinterpret_cast<const float4*>(
                        (const float*)Ap + (size_t)gr * 128 + kc + c4 * 4);
                __half2 h01 = __floats2half2_rn(v.x, v.y);
                __half2 h23 = __floats2half2_rn(v.z, v.w);
                uint2 raw;
                raw.x = *reinterpret_cast<unsigned*>(&h01);
                raw.y = *reinterpret_cast<unsigned*>(&h23);
                *reinterpret_cast<uint2*>(&sm.a[r][c4 * 4]) = raw;
            }
        }
        #pragma unroll
        for (int i = t; i < 2048; i += 256) {
            int r = i >> 5, c4 = i & 31;
            float4 v = *reinterpret_cast<const float4*>(&W[(size_t)(kc + r) * 128 + c4 * 4]);
            __half2 h01 = __floats2half2_rn(v.x, v.y);
            __half2 h23 = __floats2half2_rn(v.z, v.w);
            uint2 raw;
            raw.x = *reinterpret_cast<unsigned*>(&h01);
            raw.y = *reinterpret_cast<unsigned*>(&h23);
            *reinterpret_cast<uint2*>(&sm.w[r][c4 * 4]) = raw;
        }
        __syncthreads();

        #pragma unroll
        for (int ks = 0; ks < 4; ks++) {
            const int k0 = ks * 16;
            unsigned a0[4], a1[4];
            ldsm_x4(a0[0], a0[1], a0[2], a0[3],
                    &sm.a[wm * 32 + (lane & 15)][k0 + ((lane >> 4) & 1) * 8]);
            ldsm_x4(a1[0], a1[1], a1[2], a1[3],
                    &sm.a[wm * 32 + 16 + (lane & 15)][k0 + ((lane >> 4) & 1) * 8]);
            #pragma unroll
            for (int np = 0; np < 4; np++) {
                unsigned b[4];
                ldsm_x4_t(b[0], b[1], b[2], b[3],
                          &sm.w[k0 + (lane & 7) + ((lane >> 3) & 1) * 8]
                               [wn * 64 + np * 16 + (lane >> 4) * 8]);
                mma16816(d[0][2 * np],     a0, b[0], b[1]);
                mma16816(d[0][2 * np + 1], a0, b[2], b[3]);
                mma16816(d[1][2 * np],     a1, b[0], b[1]);
                mma16816(d[1][2 * np + 1], a1, b[2], b[3]);
            }
        }
        __syncthreads();
    }

    #pragma unroll
    for (int mi = 0; mi < 2; mi++) {
        int row = row0 + wm * 32 + mi * 16 + (lane >> 2);
        #pragma unroll
        for (int ni = 0; ni < 8; ni++) {
            int col = wn * 64 + ni * 8 + (lane & 3) * 2;
            if (row < NN) {
                __half2 h = __floats2half2_rn(d[mi][ni][0], d[mi][ni][1]);
                *reinterpret_cast<__half2*>(&C16[(size_t)row * 128 + col]) = h;
            }
            if (row + 8 < NN) {
                __half2 h = __floats2half2_rn(d[mi][ni][2], d[mi][ni][3]);
                *reinterpret_cast<__half2*>(&C16[(size_t)(row + 8) * 128 + col]) = h;
            }
        }
    }
}

// ---------------- standalone gemms ----------------
__global__ void __launch_bounds__(256) gemm32_kernel(const float* __restrict__ A,
                                                     const float* __restrict__ W,
                                                     __half* __restrict__ C16) {
    __shared__ HSmem sm;
    gemm_hmma_body<false>(sm, A, W, C16, blockIdx.x * 128, threadIdx.x);
}

__global__ void __launch_bounds__(256) gemm16_kernel(const __half* __restrict__ A16,
                                                     const float* __restrict__ W,
                                                     __half* __restrict__ C16) {
    __shared__ HSmem sm;
    gemm_hmma_body<true>(sm, A16, W, C16, blockIdx.x * 128, threadIdx.x);
}

// ---------------- CSR build (standalone, full occupancy) ----------------
__global__ void count_kernel(const int* __restrict__ dst) {
    int e = blockIdx.x * blockDim.x + threadIdx.x;
    if (e < EE) atomicAdd(&g_deg[dst[e]], 1);
}

__global__ void fill_kernel(const int* __restrict__ src, const int* __restrict__ dst) {
    int e = blockIdx.x * blockDim.x + threadIdx.x;
    if (e < EE) {
        int d = dst[e];
        int s = src[e];
        int pos = atomicAdd(&g_cursor[d], 1);
        int2 pk;
        pk.x = s;
        pk.y = __float_as_int(g_dinv[s] * g_dinv[d]);
        g_epack[pos] = pk;
    }
}

__global__ void __launch_bounds__(512) blocksum_kernel() {
    __shared__ int wsum[16];
    int t = threadIdx.x, lane = t & 31, wid = t >> 5;
    int i = blockIdx.x * 512 + t;
    int v = (i < NN) ? g_deg[i] : 0;
    #pragma unroll
    for (int d = 16; d > 0; d >>= 1)
        v += __shfl_xor_sync(0xFFFFFFFFu, v, d);
    if (lane == 0) wsum[wid] = v;
    __syncthreads();
    if (wid == 0) {
        int s = (lane < 16) ? wsum[lane] : 0;
        #pragma unroll
        for (int d = 8; d > 0; d >>= 1)
            s += __shfl_xor_sync(0xFFFFFFFFu, s, d);
        if (lane == 0) g_bsum[blockIdx.x] = s;
    }
}

__global__ void __launch_bounds__(512) rowptr_kernel() {
    __shared__ int wsum[16];
    __shared__ int s_base;
    int t = threadIdx.x, lane = t & 31, wid = t >> 5;

    int pre = 0;
    for (int j = t; j < blockIdx.x; j += 512) pre += g_bsum[j];
    #pragma unroll
    for (int d = 16; d > 0; d >>= 1)
        pre += __shfl_xor_sync(0xFFFFFFFFu, pre, d);
    if (lane == 0) wsum[wid] = pre;
    __syncthreads();
    if (t == 0) {
        int b = 0;
        #pragma unroll
        for (int w = 0; w < 16; w++) b += wsum[w];
        s_base = b;
    }
    __syncthreads();
    const int base = s_base;
    __syncthreads();

    int i = blockIdx.x * 512 + t;
    int v = (i < NN) ? g_deg[i] : 0;
    int inc = v;
    #pragma unroll
    for (int d = 1; d < 32; d <<= 1) {
        int u = __shfl_up_sync(0xFFFFFFFFu, inc, d);
        if (lane >= d) inc += u;
    }
    if (lane == 31) wsum[wid] = inc;
    __syncthreads();
    if (wid == 0) {
        int s = (lane < 16) ? wsum[lane] : 0;
        int si = s;
        #pragma unroll
        for (int d = 1; d < 16; d <<= 1) {
            int u = __shfl_up_sync(0xFFFFFFFFu, si, d);
            if (lane >= d) si += u;
        }
        if (lane < 16) wsum[lane] = si - s;
    }
    __syncthreads();
    int incl = base + wsum[wid] + inc;
    if (i < NN) {
        g_rowptr[i + 1] = incl;
        g_cursor[i] = incl - v;
        g_dinv[i] = rsqrtf((float)v + 1.0f);
        g_deg[i] = 0;
    }
    if (i == 0) g_rowptr[0] = 0;
}

// ---------------- aggregation: warp/node, fp16 in/out, packed edges ----------------
__global__ void __launch_bounds__(256) agg_kernel(const __half* __restrict__ hp16,
                                                  const float* __restrict__ bias,
                                                  __half* __restrict__ hout16) {
    int warp = (blockIdx.x * blockDim.x + threadIdx.x) >> 5;
    int lane = threadIdx.x & 31;
    if (warp >= NN) return;
    const int u = warp;
    const float du = g_dinv[u];

    uint2 sraw = *reinterpret_cast<const uint2*>(hp16 + (size_t)u * 128 + lane * 4);
    float2 s0 = __half22float2(*reinterpret_cast<__half2*>(&sraw.x));
    float2 s1 = __half22float2(*reinterpret_cast<__half2*>(&sraw.y));
    const unsigned long long selfc = pk2(du * du, du * du);
    ulonglong2 acc;
    acc.x = fma2(pk2(s0.x, s0.y), selfc, 0ULL);
    acc.y = fma2(pk2(s1.x, s1.y), selfc, 0ULL);

    const int beg = g_rowptr[u], end = g_rowptr[u + 1];
    for (int base = beg; base < end; base += 32) {
        int rem = end - base;
        int n = rem < 32 ? rem : 32;
        int s = 0; float c = 0.f;
        if (lane < n) {
            int2 pk = g_epack[base + lane];
            s = pk.x;
            c = __int_as_float(pk.y);
        }
        #pragma unroll 8
        for (int k = 0; k < n; k++) {
            int   sk = __shfl_sync(0xFFFFFFFFu, s, k);
            float ck = __shfl_sync(0xFFFFFFFFu, c, k);
            uint2 raw = __ldg(reinterpret_cast<const uint2*>(hp16 + (size_t)sk * 128) + lane);
            float2 f0 = __half22float2(*reinterpret_cast<__half2*>(&raw.x));
            float2 f1 = __half22float2(*reinterpret_cast<__half2*>(&raw.y));
            unsigned long long cc = pk2(ck, ck);
            acc.x = fma2(pk2(f0.x, f0.y), cc, acc.x);
            acc.y = fma2(pk2(f1.x, f1.y), cc, acc.y);
        }
    }
    float4 bb = *reinterpret_cast<const float4*>(&bias[lane * 4]);
    float2 a0 = upk(acc.x), a1 = upk(acc.y);
    __half2 o0 = __floats2half2_rn(fmaxf(a0.x + bb.x, 0.f), fmaxf(a0.y + bb.y, 0.f));
    __half2 o1 = __floats2half2_rn(fmaxf(a1.x + bb.z, 0.f), fmaxf(a1.y + bb.w, 0.f));
    uint2 oraw;
    oraw.x = *reinterpret_cast<unsigned*>(&o0);
    oraw.y = *reinterpret_cast<unsigned*>(&o1);
    *reinterpret_cast<uint2*>(hout16 + (size_t)u * 128 + lane * 4) = oraw;
}

// ---------------- final: HMMA [h1|h2]@Wlin + blin, fused log_softmax ----------------
// block: 128-row tile, 256 threads = 8 warps; warp w = rows w*16..w*16+15, all 48 (40+pad) cols
struct OutHS { __half a[128][72]; __half w[64][56]; };
union OutU { OutHS g; float logits[128][41]; };

__global__ void __launch_bounds__(256) gemmout_kernel(const __half* __restrict__ h1,
                                                      const __half* __restrict__ h2,
                                                      const float* __restrict__ Wlin,
                                                      const float* __restrict__ blin,
                                                      float* __restrict__ out) {
    __shared__ OutU sm;
    const int t = threadIdx.x;
    const int lane = t & 31, wid = t >> 5;
    const int row0 = blockIdx.x * 128;

    float d[6][4];
    #pragma unroll
    for (int ni = 0; ni < 6; ni++)
        #pragma unroll
        for (int p = 0; p < 4; p++) d[ni][p] = 0.f;

    #pragma unroll
    for (int chunk = 0; chunk < 4; chunk++) {
        const __half* hsrc = (chunk < 2) ? h1 : h2;
        const int koff = (chunk & 1) * 64;
        const int kc = chunk * 64;   // k offset into Wlin rows
        // stage A [128 rows][64 k] fp16
        #pragma unroll
        for (int i = t; i < 2048; i += 256) {
            int r = i >> 4, c4 = i & 15;
            int gr = row0 + r;
            uint2 raw = make_uint2(0u, 0u);
            if (gr < NN)
                raw = *reinterpret_cast<const uint2*>(&hsrc[(size_t)gr * 128 + koff + c4 * 4]);
            *reinterpret_cast<uint2*>(&sm.g.a[r][c4 * 4]) = raw;
        }
        // stage Wlin chunk [64 k][48 n] fp16, pad cols 40..55 = 0
        #pragma unroll
        for (int i = t; i < 3584; i += 256) {
            int r = i / 56, c = i % 56;
            float v = (c < 40) ? Wlin[(size_t)(kc + r) * 40 + c] : 0.f;
            sm.g.w[r][c] = __float2half(v);
        }
        __syncthreads();
        #pragma unroll
        for (int ks = 0; ks < 4; ks++) {
            const int k0 = ks * 16;
            unsigned a[4];
            ldsm_x4(a[0], a[1], a[2], a[3],
                    &sm.g.a[wid * 16 + (lane & 15)][k0 + ((lane >> 4) & 1) * 8]);
            #pragma unroll
            for (int np = 0; np < 3; np++) {
                unsigned b[4];
                ldsm_x4_t(b[0], b[1], b[2], b[3],
                          &sm.g.w[k0 + (lane & 7) + ((lane >> 3) & 1) * 8]
                               [np * 16 + (lane >> 4) * 8]);
                mma16816(d[2 * np],     a, b[0], b[1]);
                mma16816(d[2 * np + 1], a, b[2], b[3]);
            }
        }
        __syncthreads();
    }

    // logits (+bias) to smem (union reuse; mma results live in regs)
    {
        int r0 = wid * 16 + (lane >> 2);
        #pragma unroll
        for (int ni = 0; ni < 6; ni++) {
            int col = ni * 8 + (lane & 3) * 2;
            if (col < 40) {
                float b0 = blin[col], b1 = blin[col + 1];
                sm.logits[r0][col]         = d[ni][0] + b0;
                sm.logits[r0][col + 1]     = d[ni][1] + b1;
                sm.logits[r0 + 8][col]     = d[ni][2] + b0;
                sm.logits[r0 + 8][col + 1] = d[ni][3] + b1;
            }
        }
    }
    __syncthreads();

    if (t < 128) {
        int gr = row0 + t;
        if (gr < NN) {
            float m = -INFINITY;
            #pragma unroll
            for (int c = 0; c < 40; c++) m = fmaxf(m, sm.logits[t][c]);
            float s = 0.f;
            #pragma unroll
            for (int c = 0; c < 40; c++) s += expf(sm.logits[t][c] - m);
            float lse = m + logf(s);
            float* po = out + (size_t)gr * 40;
            #pragma unroll
            for (int c = 0; c < 40; c += 4) {
                float4 v = make_float4(sm.logits[t][c]     - lse,
                                       sm.logits[t][c + 1] - lse,
                                       sm.logits[t][c + 2] - lse,
                                       sm.logits[t][c + 3] - lse);
                *reinterpret_cast<float4*>(po + c) = v;
            }
        }
    }
}

// ---------------- launch ----------------
extern "C" void kernel_launch(void* const* d_in, const int* in_sizes, int n_in,
                              void* d_out, int out_size) {
    const float* x    = (const float*)d_in[0];
    const int*   ei   = (const int*)d_in[1];
    const float* W1   = (const float*)d_in[2];
    const float* b1   = (const float*)d_in[3];
    const float* W2   = (const float*)d_in[4];
    const float* b2   = (const float*)d_in[5];
    const float* Wlin = (const float*)d_in[6];
    const float* blin = (const float*)d_in[7];
    float* out = (float*)d_out;

    const int* src = ei;        // edge_index[0]
    const int* dst = ei + EE;   // edge_index[1]

    __half *p_hpre16, *p_h116, *p_h216;
    cudaGetSymbolAddress((void**)&p_hpre16, g_hpre16);
    cudaGetSymbolAddress((void**)&p_h116, g_h116);
    cudaGetSymbolAddress((void**)&p_h216, g_h216);

    const int NB_W = (NN * 32 + 255) / 256;   // warp-per-node grids

    gemm32_kernel<<<GFULL, 256>>>(x, W1, p_hpre16);                 // 1
    count_kernel<<<NB_E, 256>>>(dst);                               // 2
    blocksum_kernel<<<NBLK, 512>>>();                               // 3
    rowptr_kernel<<<NBLK, 512>>>();                                 // 4
    fill_kernel<<<NB_E, 256>>>(src, dst);                           // 5
    agg_kernel<<<NB_W, 256>>>(p_hpre16, b1, p_h116);                // 6
    gemm16_kernel<<<GFULL, 256>>>(p_h116, W2, p_hpre16);            // 7
    agg_kernel<<<NB_W, 256>>>(p_hpre16, b2, p_h216);                // 8
    gemmout_kernel<<<GFULL, 256>>>(p_h116, p_h216, Wlin, blin, out);// 9
}